// round 14
// baseline (speedup 1.0000x reference)
#include <cuda_runtime.h>
#include <cuda_bf16.h>
#include <cstdint>

#define N_   16384
#define D_   2048
#define P_   256
#define NB   32
#define NL   100
#define NSEG (NB*NL)
#define NST  3          // pipeline stages

// ---------------- scratch globals (no allocations allowed) -------------------
__device__ __nv_bfloat16 g_bhi[512 * D_];   // [W1;W2] hi
__device__ __nv_bfloat16 g_blo[512 * D_];   // [W1;W2] lo (W2 half unused)
__device__ float g_part[2 * N_ * P_];       // K-split partials of x@W1^T
__device__ float g_sumx[NSEG * D_];         // exact fp32 segsum of x
__device__ float g_mpart[4 * NSEG * P_];    // K-split partials of segsum@W2^T
__device__ float g_sum_bl2[NSEG * P_];
__device__ float g_sum_b2 [NB   * P_];
__device__ float g_M[NSEG * P_];
__device__ float g_bias[P_];
__device__ int   g_cnt[NSEG];
__device__ int   g_off[NSEG + 1];
__device__ int   g_cur[NSEG];
__device__ int   g_rows[N_];
__device__ int   g_seg[N_];
__device__ int   g_bstart[NB + 1];
__device__ int   g_is64;

// ---------------- PTX helpers ------------------------------------------------
__device__ __forceinline__ uint32_t smem_u32(const void* p) {
    uint32_t a;
    asm("{ .reg .u64 t; cvta.to.shared.u64 t, %1; cvt.u32.u64 %0, t; }" : "=r"(a) : "l"(p));
    return a;
}
__device__ __forceinline__ void cp16(uint32_t dst, const void* src) {
    asm volatile("cp.async.cg.shared.global [%0], [%1], 16;" :: "r"(dst), "l"(src));
}
#define CP_COMMIT() asm volatile("cp.async.commit_group;" ::: "memory")
#define CP_WAIT1()  asm volatile("cp.async.wait_group 1;"  ::: "memory")
#define CP_WAIT0()  asm volatile("cp.async.wait_group 0;"  ::: "memory")

__device__ __forceinline__ uint32_t swz(uint32_t o) {   // 64B-row swizzle
    return o ^ ((o >> 3) & 0x30);
}
__device__ __forceinline__ void ldm4(uint32_t addr, uint32_t& r0, uint32_t& r1,
                                     uint32_t& r2, uint32_t& r3) {
    asm volatile("ldmatrix.sync.aligned.m8n8.x4.shared.b16 {%0,%1,%2,%3}, [%4];"
                 : "=r"(r0), "=r"(r1), "=r"(r2), "=r"(r3) : "r"(addr));
}
__device__ __forceinline__ void mma16816(float* d, const uint32_t* a,
                                         const uint32_t* b) {
    asm volatile(
        "mma.sync.aligned.m16n8k16.row.col.f32.bf16.bf16.f32 "
        "{%0,%1,%2,%3}, {%4,%5,%6,%7}, {%8,%9}, {%0,%1,%2,%3};"
        : "+f"(d[0]), "+f"(d[1]), "+f"(d[2]), "+f"(d[3])
        : "r"(a[0]), "r"(a[1]), "r"(a[2]), "r"(a[3]), "r"(b[0]), "r"(b[1]));
}
__device__ __forceinline__ void sts16(uint32_t addr, uint32_t r0, uint32_t r1,
                                      uint32_t r2, uint32_t r3) {
    asm volatile("st.shared.v4.b32 [%0], {%1,%2,%3,%4};"
                 :: "r"(addr), "r"(r0), "r"(r1), "r"(r2), "r"(r3) : "memory");
}

// 4 floats -> hi bf16x2 pair + lo bf16x2 pair
__device__ __forceinline__ void pack_hilo(float4 v, uint32_t& h0, uint32_t& h1,
                                          uint32_t& l0, uint32_t& l1) {
    __nv_bfloat16 a = __float2bfloat16(v.x), b = __float2bfloat16(v.y);
    __nv_bfloat16 c = __float2bfloat16(v.z), d = __float2bfloat16(v.w);
    __nv_bfloat16 e = __float2bfloat16(v.x - __bfloat162float(a));
    __nv_bfloat16 f = __float2bfloat16(v.y - __bfloat162float(b));
    __nv_bfloat16 g = __float2bfloat16(v.z - __bfloat162float(c));
    __nv_bfloat16 h = __float2bfloat16(v.w - __bfloat162float(d));
    __nv_bfloat162 hh0(a, b), hh1(c, d), ll0(e, f), ll1(g, h);
    h0 = *(uint32_t*)&hh0; h1 = *(uint32_t*)&hh1;
    l0 = *(uint32_t*)&ll0; l1 = *(uint32_t*)&ll1;
}
__device__ __forceinline__ void packh4(float4 v, uint32_t& h0, uint32_t& h1) {
    __nv_bfloat162 p0(__float2bfloat16(v.x), __float2bfloat16(v.y));
    __nv_bfloat162 p1(__float2bfloat16(v.z), __float2bfloat16(v.w));
    h0 = *(uint32_t*)&p0; h1 = *(uint32_t*)&p1;
}

// ---------------- dtype detection + count zeroing ----------------------------
__global__ void k_detect(const int* label, const int* lb) {
    __shared__ int nz_la, nz_lb;
    int t = threadIdx.x;
    if (t == 0) { nz_la = 0; nz_lb = 0; }
    __syncthreads();
    if (t < 64) {
        int w = 2 * (t * 128) + 1;
        if (label[w] != 0) atomicOr(&nz_la, 1);
        if (lb[w]    != 0) atomicOr(&nz_lb, 1);
    }
    __syncthreads();
    if (t == 0) g_is64 = (nz_la ? 0 : 1) | (nz_lb ? 0 : 2);
    for (int i = t; i < NSEG; i += blockDim.x) g_cnt[i] = 0;
}
__device__ __forceinline__ int ld_idx(const int* p, int i, bool is64) {
    return is64 ? p[2 * i] : p[i];
}

// ---------------- seg ids, counts, batch boundaries --------------------------
__global__ void k_prep(const int* label, const int* lb) {
    bool la64 = (g_is64 & 1) != 0, lb64 = (g_is64 & 2) != 0;
    int i = blockIdx.x * blockDim.x + threadIdx.x;
    if (i < N_) {
        int la = ld_idx(label, i, la64);
        int b  = ld_idx(lb,    i, lb64);
        int s  = b * NL + la;
        g_seg[i] = s;
        atomicAdd(&g_cnt[s], 1);
    }
    if (blockIdx.x == 0 && threadIdx.x <= NB) {
        int target = threadIdx.x;
        int lo = 0, hi = N_;
        while (lo < hi) {
            int mid = (lo + hi) >> 1;
            if (ld_idx(lb, mid, lb64) < target) lo = mid + 1; else hi = mid;
        }
        g_bstart[target] = lo;
    }
}

// ---------------- prefix scan over seg counts --------------------------------
__global__ void k_scan() {
    __shared__ int sh[1024];
    int t = threadIdx.x;
    int base = t * 4;
    int c[4];
    #pragma unroll
    for (int i = 0; i < 4; i++) c[i] = (base + i < NSEG) ? g_cnt[base + i] : 0;
    int tot = c[0] + c[1] + c[2] + c[3];
    sh[t] = tot;
    __syncthreads();
    int run = tot;
    for (int d = 1; d < 1024; d <<= 1) {
        int v = (t >= d) ? sh[t - d] : 0;
        __syncthreads();
        run += v; sh[t] = run;
        __syncthreads();
    }
    int excl = (t > 0) ? sh[t - 1] : 0;
    int p = excl;
    #pragma unroll
    for (int i = 0; i < 4; i++) {
        if (base + i <= NSEG) g_off[base + i] = p;
        if (base + i <  NSEG) g_cur[base + i] = p;
        p += c[i];
    }
}

// ---------------- scatter rows by segment ------------------------------------
__global__ void k_scatter() {
    int i = blockIdx.x * blockDim.x + threadIdx.x;
    int s = g_seg[i];
    int pos = atomicAdd(&g_cur[s], 1);
    g_rows[pos] = i;
}

// ---------------- weight conversion: W1 half (critical path) -----------------
__global__ void k_convw1(const float* __restrict__ W1) {
    int i = blockIdx.x * blockDim.x + threadIdx.x;   // float4 index over 256x2048
    float4 v = ((const float4*)W1)[i];
    uint32_t h0, h1, l0, l1;
    pack_hilo(v, h0, h1, l0, l1);
    ((uint2*)g_bhi)[i] = make_uint2(h0, h1);
    ((uint2*)g_blo)[i] = make_uint2(l0, l1);
}

// ---------------- weight conversion: W2 half + bias (stream B) ---------------
__global__ void k_convw2(const float* __restrict__ W2,
                         const float* __restrict__ b1, const float* __restrict__ b2) {
    int i = blockIdx.x * blockDim.x + threadIdx.x;   // float4 index over 256x2048
    float4 v = ((const float4*)W2)[i];
    uint32_t h0, h1;
    packh4(v, h0, h1);
    ((uint2*)g_bhi)[131072 + i] = make_uint2(h0, h1);
    if (blockIdx.x == 0 && threadIdx.x < P_)
        g_bias[threadIdx.x] = b1[threadIdx.x] + b2[threadIdx.x];
}

// ---------------- segment sums: sorted float4 gather, register acc ------------
__global__ void k_segsum(const float* __restrict__ x) {
    int c0   = blockIdx.x * 64;
    int s    = blockIdx.y * 16 + (threadIdx.x >> 4);
    int col4 = (threadIdx.x & 15) * 4;
    int i0 = g_off[s], i1 = g_off[s + 1];
    float4 a0 = make_float4(0.f, 0.f, 0.f, 0.f);
    float4 a1 = make_float4(0.f, 0.f, 0.f, 0.f);
    int i = i0;
    for (; i + 2 <= i1; i += 2) {
        int r0 = g_rows[i], r1 = g_rows[i + 1];
        float4 v0 = *(const float4*)(x + (size_t)r0 * D_ + c0 + col4);
        float4 v1 = *(const float4*)(x + (size_t)r1 * D_ + c0 + col4);
        a0.x += v0.x; a0.y += v0.y; a0.z += v0.z; a0.w += v0.w;
        a1.x += v1.x; a1.y += v1.y; a1.z += v1.z; a1.w += v1.w;
    }
    if (i < i1) {
        float4 v = *(const float4*)(x + (size_t)g_rows[i] * D_ + c0 + col4);
        a0.x += v.x; a0.y += v.y; a0.z += v.z; a0.w += v.w;
    }
    float4 r = make_float4(a0.x + a1.x, a0.y + a1.y, a0.z + a1.z, a0.w + a1.w);
    *(float4*)(g_sumx + (size_t)s * D_ + c0 + col4) = r;
}

// =============== main GEMM: g_part[ks] = x @ W1^T (3-term bf16, K-split 2) ===
#define STAGE_B 24576
#define SMEM_REQ (NST * STAGE_B)

__device__ __forceinline__ void ldgA(const float* __restrict__ Arows, int kt,
                                     int tid, float4* areg) {
    int row = tid >> 2, h = tid & 3;                 // 4 thr/row, 8 floats each
    const float4* p = (const float4*)(Arows + (size_t)row * D_ + (kt << 5) + h * 8);
    areg[0] = p[0]; areg[1] = p[1];
}
__device__ __forceinline__ void stsA(uint32_t sg, int tid, const float4* areg) {
    int row = tid >> 2, h = tid & 3;
    uint32_t h0a, h1a, l0a, l1a, h0b, h1b, l0b, l1b;
    pack_hilo(areg[0], h0a, h1a, l0a, l1a);
    pack_hilo(areg[1], h0b, h1b, l0b, l1b);
    uint32_t o = swz(row * 64 + h * 16);
    sts16(sg + o,        h0a, h1a, h0b, h1b);        // A_hi
    sts16(sg + 4096 + o, l0a, l1a, l0b, l1b);        // A_lo
}
__device__ __forceinline__ void ldB(const __nv_bfloat16* Bh, const __nv_bfloat16* Bl,
                                    int kt, uint32_t sg, int tid) {
    int k0 = kt << 5;
    const char* gBh = (const char*)(Bh + k0);
    const char* gBl = (const char*)(Bl + k0);
    #pragma unroll
    for (int i = 0; i < 2; i++) {
        int idx = i * 256 + tid;
        int row = idx >> 2, c = idx & 3;
        uint32_t off = swz(row * 64 + c * 16);
        cp16(sg + 8192  + off, gBh + (size_t)row * (D_ * 2) + c * 16);
        cp16(sg + 16384 + off, gBl + (size_t)row * (D_ * 2) + c * 16);
    }
}

__global__ void __launch_bounds__(256, 3) k_gemm(const float* __restrict__ x) {
    extern __shared__ __align__(128) char smem[];
    uint32_t sbase = smem_u32(smem);
    int tid = threadIdx.x, lane = tid & 31, wid = tid >> 5;
    int wm = wid & 1, wn = wid >> 1;                 // warp grid 2(M) x 4(N)
    int n0 = blockIdx.x * 128, m0 = blockIdx.y * 64;
    int ks = blockIdx.z;                             // K-split half
    const float* Arows = x + (size_t)m0 * D_ + ks * 1024;
    const __nv_bfloat16* Bh = g_bhi + (size_t)n0 * D_ + ks * 1024;
    const __nv_bfloat16* Bl = g_blo + (size_t)n0 * D_ + ks * 1024;
    float* dst = g_part + (size_t)ks * (N_ * P_);
    const int ktn = 32;

    float d[2][4][4];
    #pragma unroll
    for (int i = 0; i < 2; i++)
        #pragma unroll
        for (int j = 0; j < 4; j++)
            #pragma unroll
            for (int k = 0; k < 4; k++) d[i][j][k] = 0.0f;

    float4 areg[2];
    ldgA(Arows, 0, tid, areg);
    stsA(sbase, tid, areg);
    ldB(Bh, Bl, 0, sbase, tid); CP_COMMIT();
    ldgA(Arows, 1, tid, areg);
    ldB(Bh, Bl, 1, sbase + STAGE_B, tid); CP_COMMIT();

    uint32_t aoff[2], boff[2];
    #pragma unroll
    for (int s = 0; s < 2; s++) {
        int arow = wm * 32 + (lane & 15);
        int acol = s * 32 + (lane >> 4) * 16;
        aoff[s] = swz(arow * 64 + acol);
        int brow = wn * 32 + ((lane >> 4) & 1) * 8 + (lane & 7);
        int bcol = s * 32 + ((lane >> 3) & 1) * 16;
        boff[s] = swz(brow * 64 + bcol);
    }

    // rotating stage bases (no % in the loop)
    uint32_t stg_c = sbase;
    uint32_t stg_s = sbase + STAGE_B;
    uint32_t stg_p = sbase + 2 * STAGE_B;

    for (int kt = 0; kt < ktn; kt++) {
        CP_WAIT1();
        __syncthreads();
        if (kt + 1 < ktn)
            stsA(stg_s, tid, areg);
        if (kt + 2 < ktn) {
            ldgA(Arows, kt + 2, tid, areg);
            ldB(Bh, Bl, kt + 2, stg_p, tid);
        }
        CP_COMMIT();

        uint32_t sAh = stg_c;
        uint32_t sAl = stg_c + 4096;
        uint32_t sBh = stg_c + 8192;
        uint32_t sBl = stg_c + 16384;
        #pragma unroll
        for (int s = 0; s < 2; s++) {
            uint32_t ah[2][4], al[2][4], bh[4][2], bl[4][2];
            #pragma unroll
            for (int f = 0; f < 2; f++)
                ldm4(sAh + f * 1024 + aoff[s], ah[f][0], ah[f][1], ah[f][2], ah[f][3]);
            #pragma unroll
            for (int p = 0; p < 2; p++)
                ldm4(sBh + p * 1024 + boff[s],
                     bh[2 * p][0], bh[2 * p][1], bh[2 * p + 1][0], bh[2 * p + 1][1]);
            #pragma unroll
            for (int p = 0; p < 2; p++)
                ldm4(sBl + p * 1024 + boff[s],
                     bl[2 * p][0], bl[2 * p][1], bl[2 * p + 1][0], bl[2 * p + 1][1]);
            #pragma unroll
            for (int f = 0; f < 2; f++)
                ldm4(sAl + f * 1024 + aoff[s], al[f][0], al[f][1], al[f][2], al[f][3]);
            #pragma unroll
            for (int mf = 0; mf < 2; mf++)
                #pragma unroll
                for (int nf = 0; nf < 4; nf++)
                    mma16816(d[mf][nf], ah[mf], bh[nf]);
            #pragma unroll
            for (int mf = 0; mf < 2; mf++)
                #pragma unroll
                for (int nf = 0; nf < 4; nf++)
                    mma16816(d[mf][nf], ah[mf], bl[nf]);
            #pragma unroll
            for (int mf = 0; mf < 2; mf++)
                #pragma unroll
                for (int nf = 0; nf < 4; nf++)
                    mma16816(d[mf][nf], al[mf], bh[nf]);
        }
        uint32_t t0 = stg_c;
        stg_c = stg_s; stg_s = stg_p; stg_p = t0;
    }
    CP_WAIT0();

    #pragma unroll
    for (int mf = 0; mf < 2; mf++) {
        int r0 = m0 + wm * 32 + mf * 16 + (lane >> 2);
        #pragma unroll
        for (int nf = 0; nf < 4; nf++) {
            int c = n0 + wn * 32 + nf * 8 + (lane & 3) * 2;
            *(float2*)(dst + (size_t)r0 * P_ + c)
                = make_float2(d[mf][nf][0], d[mf][nf][1]);
            *(float2*)(dst + (size_t)(r0 + 8) * P_ + c)
                = make_float2(d[mf][nf][2], d[mf][nf][3]);
        }
    }
}

// =============== mean GEMM: g_mpart[ks] = segsum_x @ W2^T (1-term bf16) ======
#define MSTAGE_B 12288
#define MSMEM_REQ (NST * MSTAGE_B)

__device__ __forceinline__ void stsA1(uint32_t sg, int tid, const float4* areg) {
    int row = tid >> 2, h = tid & 3;
    uint32_t h0, h1, h2, h3;
    packh4(areg[0], h0, h1);
    packh4(areg[1], h2, h3);
    sts16(sg + swz(row * 64 + h * 16), h0, h1, h2, h3);
}
__device__ __forceinline__ void ldB1(const char* Bh, int kt, uint32_t sg, int tid) {
    int k0 = kt << 6;   // bytes
    #pragma unroll
    for (int i = 0; i < 2; i++) {
        int idx = i * 256 + tid;
        int row = idx >> 2, c = idx & 3;
        uint32_t off = swz(row * 64 + c * 16);
        cp16(sg + 4096 + off, Bh + (size_t)row * (D_ * 2) + k0 + c * 16);
    }
}

__global__ void __launch_bounds__(256, 3) k_mgemm() {
    extern __shared__ __align__(128) char smem[];
    uint32_t sbase = smem_u32(smem);
    int tid = threadIdx.x, lane = tid & 31, wid = tid >> 5;
    int wm = wid & 1, wn = wid >> 1;
    int n0 = blockIdx.x * 128, m0 = blockIdx.y * 64, ks = blockIdx.z;
    const float* Arows = g_sumx + (size_t)m0 * D_ + ks * 512;
    const char*  Bh    = (const char*)(g_bhi + (size_t)(256 + n0) * D_ + ks * 512);
    float* dst = g_mpart + (size_t)ks * NSEG * P_ + (size_t)m0 * P_ + n0;
    const int ktn = 16;

    float d[2][4][4];
    #pragma unroll
    for (int i = 0; i < 2; i++)
        #pragma unroll
        for (int j = 0; j < 4; j++)
            #pragma unroll
            for (int k = 0; k < 4; k++) d[i][j][k] = 0.0f;

    float4 areg[2];
    ldgA(Arows, 0, tid, areg);
    stsA1(sbase, tid, areg);
    ldB1(Bh, 0, sbase, tid); CP_COMMIT();
    ldgA(Arows, 1, tid, areg);
    ldB1(Bh, 1, sbase + MSTAGE_B, tid); CP_COMMIT();

    uint32_t aoff[2], boff[2];
    #pragma unroll
    for (int s = 0; s < 2; s++) {
        int arow = wm * 32 + (lane & 15);
        int acol = s * 32 + (lane >> 4) * 16;
        aoff[s] = swz(arow * 64 + acol);
        int brow = wn * 32 + ((lane >> 4) & 1) * 8 + (lane & 7);
        int bcol = s * 32 + ((lane >> 3) & 1) * 16;
        boff[s] = swz(brow * 64 + bcol);
    }

    uint32_t stg_c = sbase, stg_s = sbase + MSTAGE_B, stg_p = sbase + 2 * MSTAGE_B;

    for (int kt = 0; kt < ktn; kt++) {
        CP_WAIT1();
        __syncthreads();
        if (kt + 1 < ktn)
            stsA1(stg_s, tid, areg);
        if (kt + 2 < ktn) {
            ldgA(Arows, kt + 2, tid, areg);
            ldB1(Bh, kt + 2, stg_p, tid);
        }
        CP_COMMIT();

        uint32_t sA = stg_c;
        uint32_t sB = stg_c + 4096;
        #pragma unroll
        for (int s = 0; s < 2; s++) {
            uint32_t a[2][4], b[4][2];
            #pragma unroll
            for (int f = 0; f < 2; f++)
                ldm4(sA + f * 1024 + aoff[s], a[f][0], a[f][1], a[f][2], a[f][3]);
            #pragma unroll
            for (int p = 0; p < 2; p++)
                ldm4(sB + p * 1024 + boff[s],
                     b[2 * p][0], b[2 * p][1], b[2 * p + 1][0], b[2 * p + 1][1]);
            #pragma unroll
            for (int mf = 0; mf < 2; mf++)
                #pragma unroll
                for (int nf = 0; nf < 4; nf++)
                    mma16816(d[mf][nf], a[mf], b[nf]);
        }
        uint32_t t0 = stg_c;
        stg_c = stg_s; stg_s = stg_p; stg_p = t0;
    }
    CP_WAIT0();

    #pragma unroll
    for (int mf = 0; mf < 2; mf++) {
        #pragma unroll
        for (int nf = 0; nf < 4; nf++) {
            int r = wm * 32 + mf * 16 + (lane >> 2);
            int c = wn * 32 + nf * 8 + (lane & 3) * 2;
            *(float2*)(dst + (size_t)r * P_ + c)
                = make_float2(d[mf][nf][0], d[mf][nf][1]);
            *(float2*)(dst + (size_t)(r + 8) * P_ + c)
                = make_float2(d[mf][nf][2], d[mf][nf][3]);
        }
    }
}

// ---------------- reduce K-split parts ---------------------------------------
__global__ void k_mred() {
    int i = blockIdx.x * blockDim.x + threadIdx.x;
    float s = g_mpart[i] + g_mpart[NSEG * P_ + i]
            + g_mpart[2 * NSEG * P_ + i] + g_mpart[3 * NSEG * P_ + i];
    g_sum_bl2[i] = s;
}

// ---------------- per-batch sums from per-seg sums ---------------------------
__global__ void k_sumb() {
    int b = blockIdx.x, h = blockIdx.y;
    int col = h * 128 + threadIdx.x;
    const float* base = g_sum_bl2 + (size_t)(b * NL) * P_ + col;
    float acc = 0.0f;
    #pragma unroll 4
    for (int l = 0; l < NL; l++) acc += base[(size_t)l * P_];
    g_sum_b2[b * P_ + col] = acc;
}

// ---------------- per-segment output addend ----------------------------------
__global__ void k_minv() {
    int s = blockIdx.x, t = threadIdx.x;
    int b = s / NL;
    int cb = g_bstart[b + 1] - g_bstart[b];
    int d = cb - g_cnt[s];
    float inv = (d > 0) ? (1.0f / (float)d) : 0.0f;
    float m = (g_sum_b2[b * P_ + t] - g_sum_bl2[(size_t)s * P_ + t]) * inv;
    g_M[(size_t)s * P_ + t] = m + g_bias[t];
}

// ---------------- final combine: out = p0 + p1 + M[seg] ----------------------
__global__ void k_fixup(float* __restrict__ out) {
    int i = blockIdx.x * (blockDim.x * 2) + threadIdx.x;  // float4 index, 2/thread
    #pragma unroll
    for (int u = 0; u < 2; u++) {
        int idx = i + u * blockDim.x;
        int row = idx >> 6;
        int c4  = (idx & 63) << 2;
        int s = g_seg[row];
        float4 p0 = *(const float4*)(g_part + (size_t)row * P_ + c4);
        float4 p1 = *(const float4*)(g_part + (size_t)(N_ * P_) + (size_t)row * P_ + c4);
        float4 m  = *(const float4*)(g_M + (size_t)s * P_ + c4);
        float4 o;
        o.x = p0.x + p1.x + m.x;
        o.y = p0.y + p1.y + m.y;
        o.z = p0.z + p1.z + m.z;
        o.w = p0.w + p1.w + m.w;
        *(float4*)(out + (size_t)row * P_ + c4) = o;
    }
}

// ---------------- launch: two-stream fork/join inside graph capture ----------
extern "C" void kernel_launch(void* const* d_in, const int* in_sizes, int n_in,
                              void* d_out, int out_size) {
    const float* x     = (const float*)d_in[0];
    const int*   label = (const int*)  d_in[1];
    const int*   lb    = (const int*)  d_in[2];
    const float* W1_w  = (const float*)d_in[3];
    const float* W1_b  = (const float*)d_in[4];
    const float* W2_w  = (const float*)d_in[5];
    const float* W2_b  = (const float*)d_in[6];
    float* out = (float*)d_out;

    cudaFuncSetAttribute(k_gemm,  cudaFuncAttributeMaxDynamicSharedMemorySize, SMEM_REQ);
    cudaFuncSetAttribute(k_mgemm, cudaFuncAttributeMaxDynamicSharedMemorySize, MSMEM_REQ);

    cudaStream_t sB;
    cudaStreamCreateWithFlags(&sB, cudaStreamNonBlocking);
    cudaEvent_t evFork, evB;
    cudaEventCreateWithFlags(&evFork, cudaEventDisableTiming);
    cudaEventCreateWithFlags(&evB,    cudaEventDisableTiming);

    // fork aux stream from the capturing (default) stream
    cudaEventRecord(evFork, 0);
    cudaStreamWaitEvent(sB, evFork, 0);

    // ---- stream B: segment bookkeeping + W2 conversion + mean pipeline ----
    k_detect <<<1, 256, 0, sB>>>(label, lb);
    k_prep   <<<N_ / 256, 256, 0, sB>>>(label, lb);
    k_scan   <<<1, 1024, 0, sB>>>();
    k_scatter<<<N_ / 256, 256, 0, sB>>>();
    k_segsum <<<dim3(D_ / 64, NSEG / 16), 256, 0, sB>>>(x);
    k_convw2 <<<(256 * D_ / 4) / 256, 256, 0, sB>>>(W2_w, W1_b, W2_b);
    k_mgemm  <<<dim3(2, NSEG / 64, 4), 256, MSMEM_REQ, sB>>>();
    k_mred   <<<(NSEG * P_) / 256, 256, 0, sB>>>();
    k_sumb   <<<dim3(NB, 2), 128, 0, sB>>>();
    k_minv   <<<NSEG, 256, 0, sB>>>();
    cudaEventRecord(evB, sB);

    // ---- default stream: W1 conversion, then K-split main GEMM ----
    k_convw1<<<(256 * D_ / 4) / 256, 256>>>(W1_w);
    k_gemm<<<dim3(2, 256, 2), 256, SMEM_REQ>>>(x);

    // join: fixup needs g_part (default) and g_M/g_seg (stream B)
    cudaStreamWaitEvent(0, evB, 0);
    k_fixup<<<(N_ * P_ / 4) / 1024, 512>>>(out);
}

// round 15
// speedup vs baseline: 1.0596x; 1.0596x over previous
#include <cuda_runtime.h>
#include <cuda_bf16.h>
#include <cstdint>

#define N_   16384
#define D_   2048
#define P_   256
#define NB   32
#define NL   100
#define NSEG (NB*NL)
#define NST  3          // pipeline stages

// ---------------- scratch globals (no allocations allowed) -------------------
__device__ __nv_bfloat16 g_bhi[512 * D_];   // [W1;W2] hi
__device__ __nv_bfloat16 g_blo[512 * D_];   // [W1;W2] lo (W2 half unused)
__device__ float g_sumx[NSEG * D_];         // exact fp32 segsum of x
__device__ float g_mpart[4 * NSEG * P_];    // K-split partials of segsum@W2^T
__device__ float g_sum_bl2[NSEG * P_];
__device__ float g_sum_b2 [NB   * P_];
__device__ float g_M[NSEG * P_];
__device__ float g_bias[P_];
__device__ int   g_cnt[NSEG];
__device__ int   g_off[NSEG + 1];
__device__ int   g_cur[NSEG];
__device__ int   g_rows[N_];
__device__ int   g_seg[N_];
__device__ int   g_bstart[NB + 1];
__device__ int   g_is64;

// ---------------- PTX helpers ------------------------------------------------
__device__ __forceinline__ uint32_t smem_u32(const void* p) {
    uint32_t a;
    asm("{ .reg .u64 t; cvta.to.shared.u64 t, %1; cvt.u32.u64 %0, t; }" : "=r"(a) : "l"(p));
    return a;
}
__device__ __forceinline__ void cp16(uint32_t dst, const void* src) {
    asm volatile("cp.async.cg.shared.global [%0], [%1], 16;" :: "r"(dst), "l"(src));
}
#define CP_COMMIT() asm volatile("cp.async.commit_group;" ::: "memory")
#define CP_WAIT1()  asm volatile("cp.async.wait_group 1;"  ::: "memory")
#define CP_WAIT0()  asm volatile("cp.async.wait_group 0;"  ::: "memory")

__device__ __forceinline__ uint32_t swz(uint32_t o) {   // 64B-row swizzle
    return o ^ ((o >> 3) & 0x30);
}
__device__ __forceinline__ void ldm4(uint32_t addr, uint32_t& r0, uint32_t& r1,
                                     uint32_t& r2, uint32_t& r3) {
    asm volatile("ldmatrix.sync.aligned.m8n8.x4.shared.b16 {%0,%1,%2,%3}, [%4];"
                 : "=r"(r0), "=r"(r1), "=r"(r2), "=r"(r3) : "r"(addr));
}
__device__ __forceinline__ void mma16816(float* d, const uint32_t* a,
                                         const uint32_t* b) {
    asm volatile(
        "mma.sync.aligned.m16n8k16.row.col.f32.bf16.bf16.f32 "
        "{%0,%1,%2,%3}, {%4,%5,%6,%7}, {%8,%9}, {%0,%1,%2,%3};"
        : "+f"(d[0]), "+f"(d[1]), "+f"(d[2]), "+f"(d[3])
        : "r"(a[0]), "r"(a[1]), "r"(a[2]), "r"(a[3]), "r"(b[0]), "r"(b[1]));
}
__device__ __forceinline__ void sts16(uint32_t addr, uint32_t r0, uint32_t r1,
                                      uint32_t r2, uint32_t r3) {
    asm volatile("st.shared.v4.b32 [%0], {%1,%2,%3,%4};"
                 :: "r"(addr), "r"(r0), "r"(r1), "r"(r2), "r"(r3) : "memory");
}

// 4 floats -> hi bf16x2 pair + lo bf16x2 pair
__device__ __forceinline__ void pack_hilo(float4 v, uint32_t& h0, uint32_t& h1,
                                          uint32_t& l0, uint32_t& l1) {
    __nv_bfloat16 a = __float2bfloat16(v.x), b = __float2bfloat16(v.y);
    __nv_bfloat16 c = __float2bfloat16(v.z), d = __float2bfloat16(v.w);
    __nv_bfloat16 e = __float2bfloat16(v.x - __bfloat162float(a));
    __nv_bfloat16 f = __float2bfloat16(v.y - __bfloat162float(b));
    __nv_bfloat16 g = __float2bfloat16(v.z - __bfloat162float(c));
    __nv_bfloat16 h = __float2bfloat16(v.w - __bfloat162float(d));
    __nv_bfloat162 hh0(a, b), hh1(c, d), ll0(e, f), ll1(g, h);
    h0 = *(uint32_t*)&hh0; h1 = *(uint32_t*)&hh1;
    l0 = *(uint32_t*)&ll0; l1 = *(uint32_t*)&ll1;
}
__device__ __forceinline__ void packh4(float4 v, uint32_t& h0, uint32_t& h1) {
    __nv_bfloat162 p0(__float2bfloat16(v.x), __float2bfloat16(v.y));
    __nv_bfloat162 p1(__float2bfloat16(v.z), __float2bfloat16(v.w));
    h0 = *(uint32_t*)&p0; h1 = *(uint32_t*)&p1;
}

// ---------------- dtype detection + count zeroing ----------------------------
__global__ void k_detect(const int* label, const int* lb) {
    __shared__ int nz_la, nz_lb;
    int t = threadIdx.x;
    if (t == 0) { nz_la = 0; nz_lb = 0; }
    __syncthreads();
    if (t < 64) {
        int w = 2 * (t * 128) + 1;
        if (label[w] != 0) atomicOr(&nz_la, 1);
        if (lb[w]    != 0) atomicOr(&nz_lb, 1);
    }
    __syncthreads();
    if (t == 0) g_is64 = (nz_la ? 0 : 1) | (nz_lb ? 0 : 2);
    for (int i = t; i < NSEG; i += blockDim.x) g_cnt[i] = 0;
}
__device__ __forceinline__ int ld_idx(const int* p, int i, bool is64) {
    return is64 ? p[2 * i] : p[i];
}

// ---------------- seg ids, counts, batch boundaries --------------------------
__global__ void k_prep(const int* label, const int* lb) {
    bool la64 = (g_is64 & 1) != 0, lb64 = (g_is64 & 2) != 0;
    int i = blockIdx.x * blockDim.x + threadIdx.x;
    if (i < N_) {
        int la = ld_idx(label, i, la64);
        int b  = ld_idx(lb,    i, lb64);
        int s  = b * NL + la;
        g_seg[i] = s;
        atomicAdd(&g_cnt[s], 1);
    }
    if (blockIdx.x == 0 && threadIdx.x <= NB) {
        int target = threadIdx.x;
        int lo = 0, hi = N_;
        while (lo < hi) {
            int mid = (lo + hi) >> 1;
            if (ld_idx(lb, mid, lb64) < target) lo = mid + 1; else hi = mid;
        }
        g_bstart[target] = lo;
    }
}

// ---------------- prefix scan over seg counts --------------------------------
__global__ void k_scan() {
    __shared__ int sh[1024];
    int t = threadIdx.x;
    int base = t * 4;
    int c[4];
    #pragma unroll
    for (int i = 0; i < 4; i++) c[i] = (base + i < NSEG) ? g_cnt[base + i] : 0;
    int tot = c[0] + c[1] + c[2] + c[3];
    sh[t] = tot;
    __syncthreads();
    int run = tot;
    for (int d = 1; d < 1024; d <<= 1) {
        int v = (t >= d) ? sh[t - d] : 0;
        __syncthreads();
        run += v; sh[t] = run;
        __syncthreads();
    }
    int excl = (t > 0) ? sh[t - 1] : 0;
    int p = excl;
    #pragma unroll
    for (int i = 0; i < 4; i++) {
        if (base + i <= NSEG) g_off[base + i] = p;
        if (base + i <  NSEG) g_cur[base + i] = p;
        p += c[i];
    }
}

// ---------------- scatter rows by segment ------------------------------------
__global__ void k_scatter() {
    int i = blockIdx.x * blockDim.x + threadIdx.x;
    int s = g_seg[i];
    int pos = atomicAdd(&g_cur[s], 1);
    g_rows[pos] = i;
}

// ---------------- weight hi/lo conversion ------------------------------------
__global__ void k_convw(const float* __restrict__ W1, const float* __restrict__ W2,
                        const float* __restrict__ b1, const float* __restrict__ b2) {
    int i = blockIdx.x * blockDim.x + threadIdx.x;   // float4 index over 512x2048
    int e = i * 4;
    int row = e >> 11;
    int col = e & 2047;
    const float* src = (row < 256) ? (W1 + (size_t)row * D_ + col)
                                   : (W2 + (size_t)(row - 256) * D_ + col);
    float4 v = *(const float4*)src;
    uint32_t h0, h1, l0, l1;
    pack_hilo(v, h0, h1, l0, l1);
    ((uint2*)g_bhi)[i] = make_uint2(h0, h1);
    ((uint2*)g_blo)[i] = make_uint2(l0, l1);
    if (blockIdx.x == 0 && threadIdx.x < P_)
        g_bias[threadIdx.x] = b1[threadIdx.x] + b2[threadIdx.x];
}

// ---------------- segment sums: sorted float4 gather, register acc ------------
__global__ void k_segsum(const float* __restrict__ x) {
    int c0   = blockIdx.x * 64;
    int s    = blockIdx.y * 16 + (threadIdx.x >> 4);
    int col4 = (threadIdx.x & 15) * 4;
    int i0 = g_off[s], i1 = g_off[s + 1];
    float4 a0 = make_float4(0.f, 0.f, 0.f, 0.f);
    float4 a1 = make_float4(0.f, 0.f, 0.f, 0.f);
    int i = i0;
    for (; i + 2 <= i1; i += 2) {
        int r0 = g_rows[i], r1 = g_rows[i + 1];
        float4 v0 = *(const float4*)(x + (size_t)r0 * D_ + c0 + col4);
        float4 v1 = *(const float4*)(x + (size_t)r1 * D_ + c0 + col4);
        a0.x += v0.x; a0.y += v0.y; a0.z += v0.z; a0.w += v0.w;
        a1.x += v1.x; a1.y += v1.y; a1.z += v1.z; a1.w += v1.w;
    }
    if (i < i1) {
        float4 v = *(const float4*)(x + (size_t)g_rows[i] * D_ + c0 + col4);
        a0.x += v.x; a0.y += v.y; a0.z += v.z; a0.w += v.w;
    }
    float4 r = make_float4(a0.x + a1.x, a0.y + a1.y, a0.z + a1.z, a0.w + a1.w);
    *(float4*)(g_sumx + (size_t)s * D_ + c0 + col4) = r;
}

// =============== main GEMM: out = x @ W1^T (3-term bf16), plain store ========
#define STAGE_B 24576
#define SMEM_REQ (NST * STAGE_B)

__device__ __forceinline__ void ldgA(const float* __restrict__ Arows, int kt,
                                     int tid, float4* areg) {
    int row = tid >> 2, h = tid & 3;                 // 4 thr/row, 8 floats each
    const float4* p = (const float4*)(Arows + (size_t)row * D_ + (kt << 5) + h * 8);
    areg[0] = p[0]; areg[1] = p[1];
}
__device__ __forceinline__ void stsA(uint32_t sg, int tid, const float4* areg) {
    int row = tid >> 2, h = tid & 3;
    uint32_t h0a, h1a, l0a, l1a, h0b, h1b, l0b, l1b;
    pack_hilo(areg[0], h0a, h1a, l0a, l1a);
    pack_hilo(areg[1], h0b, h1b, l0b, l1b);
    uint32_t o = swz(row * 64 + h * 16);
    sts16(sg + o,        h0a, h1a, h0b, h1b);        // A_hi
    sts16(sg + 4096 + o, l0a, l1a, l0b, l1b);        // A_lo
}
__device__ __forceinline__ void ldB(const __nv_bfloat16* Bh, const __nv_bfloat16* Bl,
                                    int kt, uint32_t sg, int tid) {
    int k0 = kt << 5;
    const char* gBh = (const char*)(Bh + k0);
    const char* gBl = (const char*)(Bl + k0);
    #pragma unroll
    for (int i = 0; i < 2; i++) {
        int idx = i * 256 + tid;
        int row = idx >> 2, c = idx & 3;
        uint32_t off = swz(row * 64 + c * 16);
        cp16(sg + 8192  + off, gBh + (size_t)row * (D_ * 2) + c * 16);
        cp16(sg + 16384 + off, gBl + (size_t)row * (D_ * 2) + c * 16);
    }
}

__global__ void __launch_bounds__(256, 3) k_gemm(const float* __restrict__ x,
                                                 float* __restrict__ out) {
    extern __shared__ __align__(128) char smem[];
    uint32_t sbase = smem_u32(smem);
    int tid = threadIdx.x, lane = tid & 31, wid = tid >> 5;
    int wm = wid & 1, wn = wid >> 1;                 // warp grid 2(M) x 4(N)
    int n0 = blockIdx.x * 128, m0 = blockIdx.y * 64;
    const float* Arows = x + (size_t)m0 * D_;
    const __nv_bfloat16* Bh = g_bhi + (size_t)n0 * D_;
    const __nv_bfloat16* Bl = g_blo + (size_t)n0 * D_;
    const int ktn = 64;

    float d[2][4][4];
    #pragma unroll
    for (int i = 0; i < 2; i++)
        #pragma unroll
        for (int j = 0; j < 4; j++)
            #pragma unroll
            for (int k = 0; k < 4; k++) d[i][j][k] = 0.0f;

    float4 areg[2];
    ldgA(Arows, 0, tid, areg);
    stsA(sbase, tid, areg);
    ldB(Bh, Bl, 0, sbase, tid); CP_COMMIT();
    ldgA(Arows, 1, tid, areg);
    ldB(Bh, Bl, 1, sbase + STAGE_B, tid); CP_COMMIT();

    uint32_t aoff[2], boff[2];
    #pragma unroll
    for (int s = 0; s < 2; s++) {
        int arow = wm * 32 + (lane & 15);
        int acol = s * 32 + (lane >> 4) * 16;
        aoff[s] = swz(arow * 64 + acol);
        int brow = wn * 32 + ((lane >> 4) & 1) * 8 + (lane & 7);
        int bcol = s * 32 + ((lane >> 3) & 1) * 16;
        boff[s] = swz(brow * 64 + bcol);
    }

    // rotating stage bases (no % in the loop)
    uint32_t stg_c = sbase;                   // compute stage (kt)
    uint32_t stg_s = sbase + STAGE_B;         // store-A stage (kt+1)
    uint32_t stg_p = sbase + 2 * STAGE_B;     // prefetch stage (kt+2)

    for (int kt = 0; kt < ktn; kt++) {
        CP_WAIT1();
        __syncthreads();
        if (kt + 1 < ktn)
            stsA(stg_s, tid, areg);
        if (kt + 2 < ktn) {
            ldgA(Arows, kt + 2, tid, areg);
            ldB(Bh, Bl, kt + 2, stg_p, tid);
        }
        CP_COMMIT();

        uint32_t sAh = stg_c;
        uint32_t sAl = stg_c + 4096;
        uint32_t sBh = stg_c + 8192;
        uint32_t sBl = stg_c + 16384;
        #pragma unroll
        for (int s = 0; s < 2; s++) {
            uint32_t ah[2][4], al[2][4], bh[4][2], bl[4][2];
            #pragma unroll
            for (int f = 0; f < 2; f++)
                ldm4(sAh + f * 1024 + aoff[s], ah[f][0], ah[f][1], ah[f][2], ah[f][3]);
            #pragma unroll
            for (int p = 0; p < 2; p++)
                ldm4(sBh + p * 1024 + boff[s],
                     bh[2 * p][0], bh[2 * p][1], bh[2 * p + 1][0], bh[2 * p + 1][1]);
            #pragma unroll
            for (int p = 0; p < 2; p++)
                ldm4(sBl + p * 1024 + boff[s],
                     bl[2 * p][0], bl[2 * p][1], bl[2 * p + 1][0], bl[2 * p + 1][1]);
            #pragma unroll
            for (int f = 0; f < 2; f++)
                ldm4(sAl + f * 1024 + aoff[s], al[f][0], al[f][1], al[f][2], al[f][3]);
            #pragma unroll
            for (int mf = 0; mf < 2; mf++)
                #pragma unroll
                for (int nf = 0; nf < 4; nf++)
                    mma16816(d[mf][nf], ah[mf], bh[nf]);
            #pragma unroll
            for (int mf = 0; mf < 2; mf++)
                #pragma unroll
                for (int nf = 0; nf < 4; nf++)
                    mma16816(d[mf][nf], ah[mf], bl[nf]);
            #pragma unroll
            for (int mf = 0; mf < 2; mf++)
                #pragma unroll
                for (int nf = 0; nf < 4; nf++)
                    mma16816(d[mf][nf], al[mf], bh[nf]);
        }
        // rotate stages
        uint32_t t0 = stg_c;
        stg_c = stg_s; stg_s = stg_p; stg_p = t0;
    }
    CP_WAIT0();

    // plain store; g_M added later by k_fixup (computed concurrently)
    #pragma unroll
    for (int mf = 0; mf < 2; mf++) {
        int r0 = m0 + wm * 32 + mf * 16 + (lane >> 2);
        #pragma unroll
        for (int nf = 0; nf < 4; nf++) {
            int c = n0 + wn * 32 + nf * 8 + (lane & 3) * 2;
            *(float2*)(out + (size_t)r0 * P_ + c)
                = make_float2(d[mf][nf][0], d[mf][nf][1]);
            *(float2*)(out + (size_t)(r0 + 8) * P_ + c)
                = make_float2(d[mf][nf][2], d[mf][nf][3]);
        }
    }
}

// =============== mean GEMM: g_mpart[ks] = segsum_x @ W2^T (1-term bf16) ======
#define MSTAGE_B 12288
#define MSMEM_REQ (NST * MSTAGE_B)

__device__ __forceinline__ void stsA1(uint32_t sg, int tid, const float4* areg) {
    int row = tid >> 2, h = tid & 3;
    uint32_t h0, h1, h2, h3;
    packh4(areg[0], h0, h1);
    packh4(areg[1], h2, h3);
    sts16(sg + swz(row * 64 + h * 16), h0, h1, h2, h3);
}
__device__ __forceinline__ void ldB1(const char* Bh, int kt, uint32_t sg, int tid) {
    int k0 = kt << 6;   // bytes
    #pragma unroll
    for (int i = 0; i < 2; i++) {
        int idx = i * 256 + tid;
        int row = idx >> 2, c = idx & 3;
        uint32_t off = swz(row * 64 + c * 16);
        cp16(sg + 4096 + off, Bh + (size_t)row * (D_ * 2) + k0 + c * 16);
    }
}

__global__ void __launch_bounds__(256, 3) k_mgemm() {
    extern __shared__ __align__(128) char smem[];
    uint32_t sbase = smem_u32(smem);
    int tid = threadIdx.x, lane = tid & 31, wid = tid >> 5;
    int wm = wid & 1, wn = wid >> 1;
    int n0 = blockIdx.x * 128, m0 = blockIdx.y * 64, ks = blockIdx.z;
    const float* Arows = g_sumx + (size_t)m0 * D_ + ks * 512;
    const char*  Bh    = (const char*)(g_bhi + (size_t)(256 + n0) * D_ + ks * 512);
    float* dst = g_mpart + (size_t)ks * NSEG * P_ + (size_t)m0 * P_ + n0;
    const int ktn = 16;

    float d[2][4][4];
    #pragma unroll
    for (int i = 0; i < 2; i++)
        #pragma unroll
        for (int j = 0; j < 4; j++)
            #pragma unroll
            for (int k = 0; k < 4; k++) d[i][j][k] = 0.0f;

    float4 areg[2];
    ldgA(Arows, 0, tid, areg);
    stsA1(sbase, tid, areg);
    ldB1(Bh, 0, sbase, tid); CP_COMMIT();
    ldgA(Arows, 1, tid, areg);
    ldB1(Bh, 1, sbase + MSTAGE_B, tid); CP_COMMIT();

    uint32_t aoff[2], boff[2];
    #pragma unroll
    for (int s = 0; s < 2; s++) {
        int arow = wm * 32 + (lane & 15);
        int acol = s * 32 + (lane >> 4) * 16;
        aoff[s] = swz(arow * 64 + acol);
        int brow = wn * 32 + ((lane >> 4) & 1) * 8 + (lane & 7);
        int bcol = s * 32 + ((lane >> 3) & 1) * 16;
        boff[s] = swz(brow * 64 + bcol);
    }

    uint32_t stg_c = sbase, stg_s = sbase + MSTAGE_B, stg_p = sbase + 2 * MSTAGE_B;

    for (int kt = 0; kt < ktn; kt++) {
        CP_WAIT1();
        __syncthreads();
        if (kt + 1 < ktn)
            stsA1(stg_s, tid, areg);
        if (kt + 2 < ktn) {
            ldgA(Arows, kt + 2, tid, areg);
            ldB1(Bh, kt + 2, stg_p, tid);
        }
        CP_COMMIT();

        uint32_t sA = stg_c;
        uint32_t sB = stg_c + 4096;
        #pragma unroll
        for (int s = 0; s < 2; s++) {
            uint32_t a[2][4], b[4][2];
            #pragma unroll
            for (int f = 0; f < 2; f++)
                ldm4(sA + f * 1024 + aoff[s], a[f][0], a[f][1], a[f][2], a[f][3]);
            #pragma unroll
            for (int p = 0; p < 2; p++)
                ldm4(sB + p * 1024 + boff[s],
                     b[2 * p][0], b[2 * p][1], b[2 * p + 1][0], b[2 * p + 1][1]);
            #pragma unroll
            for (int mf = 0; mf < 2; mf++)
                #pragma unroll
                for (int nf = 0; nf < 4; nf++)
                    mma16816(d[mf][nf], a[mf], b[nf]);
        }
        uint32_t t0 = stg_c;
        stg_c = stg_s; stg_s = stg_p; stg_p = t0;
    }
    CP_WAIT0();

    #pragma unroll
    for (int mf = 0; mf < 2; mf++) {
        #pragma unroll
        for (int nf = 0; nf < 4; nf++) {
            int r = wm * 32 + mf * 16 + (lane >> 2);
            int c = wn * 32 + nf * 8 + (lane & 3) * 2;
            *(float2*)(dst + (size_t)r * P_ + c)
                = make_float2(d[mf][nf][0], d[mf][nf][1]);
            *(float2*)(dst + (size_t)(r + 8) * P_ + c)
                = make_float2(d[mf][nf][2], d[mf][nf][3]);
        }
    }
}

// ---------------- reduce K-split parts ---------------------------------------
__global__ void k_mred() {
    int i = blockIdx.x * blockDim.x + threadIdx.x;
    float s = g_mpart[i] + g_mpart[NSEG * P_ + i]
            + g_mpart[2 * NSEG * P_ + i] + g_mpart[3 * NSEG * P_ + i];
    g_sum_bl2[i] = s;
}

// ---------------- per-batch sums from per-seg sums ---------------------------
__global__ void k_sumb() {
    int b = blockIdx.x, h = blockIdx.y;
    int col = h * 128 + threadIdx.x;
    const float* base = g_sum_bl2 + (size_t)(b * NL) * P_ + col;
    float acc = 0.0f;
    #pragma unroll 4
    for (int l = 0; l < NL; l++) acc += base[(size_t)l * P_];
    g_sum_b2[b * P_ + col] = acc;
}

// ---------------- per-segment output addend ----------------------------------
__global__ void k_minv() {
    int s = blockIdx.x, t = threadIdx.x;
    int b = s / NL;
    int cb = g_bstart[b + 1] - g_bstart[b];
    int d = cb - g_cnt[s];
    float inv = (d > 0) ? (1.0f / (float)d) : 0.0f;
    float m = (g_sum_b2[b * P_ + t] - g_sum_bl2[(size_t)s * P_ + t]) * inv;
    g_M[(size_t)s * P_ + t] = m + g_bias[t];
}

// ---------------- final gather-add -------------------------------------------
__global__ void k_fixup(float* __restrict__ out) {
    int i = blockIdx.x * blockDim.x + threadIdx.x;   // float4 index
    int row = i >> 6;
    int c4  = (i & 63) << 2;
    int s = g_seg[row];
    float4 o = *(float4*)(out + (size_t)row * P_ + c4);
    float4 m = *(const float4*)(g_M + (size_t)s * P_ + c4);
    o.x += m.x; o.y += m.y; o.z += m.z; o.w += m.w;
    *(float4*)(out + (size_t)row * P_ + c4) = o;
}

// ---------------- launch: two-stream fork/join inside graph capture ----------
extern "C" void kernel_launch(void* const* d_in, const int* in_sizes, int n_in,
                              void* d_out, int out_size) {
    const float* x     = (const float*)d_in[0];
    const int*   label = (const int*)  d_in[1];
    const int*   lb    = (const int*)  d_in[2];
    const float* W1_w  = (const float*)d_in[3];
    const float* W1_b  = (const float*)d_in[4];
    const float* W2_w  = (const float*)d_in[5];
    const float* W2_b  = (const float*)d_in[6];
    float* out = (float*)d_out;

    cudaFuncSetAttribute(k_gemm,  cudaFuncAttributeMaxDynamicSharedMemorySize, SMEM_REQ);
    cudaFuncSetAttribute(k_mgemm, cudaFuncAttributeMaxDynamicSharedMemorySize, MSMEM_REQ);

    cudaStream_t sB;
    cudaStreamCreateWithFlags(&sB, cudaStreamNonBlocking);
    cudaEvent_t evFork, evConvw, evB;
    cudaEventCreateWithFlags(&evFork,  cudaEventDisableTiming);
    cudaEventCreateWithFlags(&evConvw, cudaEventDisableTiming);
    cudaEventCreateWithFlags(&evB,     cudaEventDisableTiming);

    // fork aux stream from the capturing (default) stream
    cudaEventRecord(evFork, 0);
    cudaStreamWaitEvent(sB, evFork, 0);

    // ---- stream B: segment bookkeeping + mean pipeline ----
    k_detect <<<1, 256, 0, sB>>>(label, lb);
    k_prep   <<<N_ / 256, 256, 0, sB>>>(label, lb);
    k_scan   <<<1, 1024, 0, sB>>>();
    k_scatter<<<N_ / 256, 256, 0, sB>>>();
    k_segsum <<<dim3(D_ / 64, NSEG / 16), 256, 0, sB>>>(x);

    // ---- default stream: weight conversion, then main GEMM ----
    k_convw<<<(512 * D_ / 4) / 256, 256>>>(W1_w, W2_w, W1_b, W2_b);
    cudaEventRecord(evConvw, 0);
    cudaStreamWaitEvent(sB, evConvw, 0);   // mgemm needs g_bhi (W2 half) + g_bias

    k_mgemm<<<dim3(2, NSEG / 64, 4), 256, MSMEM_REQ, sB>>>();
    k_mred <<<(NSEG * P_) / 256, 256, 0, sB>>>();
    k_sumb <<<dim3(NB, 2), 128, 0, sB>>>();
    k_minv <<<NSEG, 256, 0, sB>>>();
    cudaEventRecord(evB, sB);

    k_gemm<<<dim3(2, 256), 256, SMEM_REQ>>>(x, out);

    // join: fixup needs both out (default) and g_M/g_seg (stream B)
    cudaStreamWaitEvent(0, evB, 0);
    k_fixup<<<(N_ * P_ / 4) / 256, 256>>>(out);
}

// round 16
// speedup vs baseline: 1.0712x; 1.0109x over previous
#include <cuda_runtime.h>
#include <cuda_bf16.h>
#include <cstdint>

#define N_   16384
#define D_   2048
#define P_   256
#define NB   32
#define NL   100
#define NSEG (NB*NL)
#define NST  3          // pipeline stages

// ---------------- scratch globals (no allocations allowed) -------------------
__device__ __nv_bfloat16 g_bhi[512 * D_];   // [W1;W2] hi
__device__ __nv_bfloat16 g_blo[512 * D_];   // [W1;W2] lo (W2 half unused)
__device__ float g_sumx[NSEG * D_];         // exact fp32 segsum of x
__device__ float g_mpart[4 * NSEG * P_];    // K-split partials of segsum@W2^T
__device__ float g_sum_bl2[NSEG * P_];
__device__ float g_sum_b2 [NB   * P_];
__device__ float g_M[NSEG * P_];
__device__ float g_bias[P_];
__device__ int   g_cnt[NSEG];
__device__ int   g_off[NSEG + 1];
__device__ int   g_cur[NSEG];
__device__ int   g_rows[N_];
__device__ int   g_seg[N_];
__device__ int   g_bstart[NB + 1];
__device__ int   g_is64;

// ---------------- PTX helpers ------------------------------------------------
__device__ __forceinline__ uint32_t smem_u32(const void* p) {
    uint32_t a;
    asm("{ .reg .u64 t; cvta.to.shared.u64 t, %1; cvt.u32.u64 %0, t; }" : "=r"(a) : "l"(p));
    return a;
}
__device__ __forceinline__ void cp16(uint32_t dst, const void* src) {
    asm volatile("cp.async.cg.shared.global [%0], [%1], 16;" :: "r"(dst), "l"(src));
}
#define CP_COMMIT() asm volatile("cp.async.commit_group;" ::: "memory")
#define CP_WAIT1()  asm volatile("cp.async.wait_group 1;"  ::: "memory")
#define CP_WAIT0()  asm volatile("cp.async.wait_group 0;"  ::: "memory")

__device__ __forceinline__ uint32_t swz(uint32_t o) {   // 64B-row swizzle
    return o ^ ((o >> 3) & 0x30);
}
__device__ __forceinline__ void ldm4(uint32_t addr, uint32_t& r0, uint32_t& r1,
                                     uint32_t& r2, uint32_t& r3) {
    asm volatile("ldmatrix.sync.aligned.m8n8.x4.shared.b16 {%0,%1,%2,%3}, [%4];"
                 : "=r"(r0), "=r"(r1), "=r"(r2), "=r"(r3) : "r"(addr));
}
__device__ __forceinline__ void mma16816(float* d, const uint32_t* a,
                                         const uint32_t* b) {
    asm volatile(
        "mma.sync.aligned.m16n8k16.row.col.f32.bf16.bf16.f32 "
        "{%0,%1,%2,%3}, {%4,%5,%6,%7}, {%8,%9}, {%0,%1,%2,%3};"
        : "+f"(d[0]), "+f"(d[1]), "+f"(d[2]), "+f"(d[3])
        : "r"(a[0]), "r"(a[1]), "r"(a[2]), "r"(a[3]), "r"(b[0]), "r"(b[1]));
}
__device__ __forceinline__ void sts16(uint32_t addr, uint32_t r0, uint32_t r1,
                                      uint32_t r2, uint32_t r3) {
    asm volatile("st.shared.v4.b32 [%0], {%1,%2,%3,%4};"
                 :: "r"(addr), "r"(r0), "r"(r1), "r"(r2), "r"(r3) : "memory");
}

// 4 floats -> hi bf16x2 pair + lo bf16x2 pair
__device__ __forceinline__ void pack_hilo(float4 v, uint32_t& h0, uint32_t& h1,
                                          uint32_t& l0, uint32_t& l1) {
    __nv_bfloat16 a = __float2bfloat16(v.x), b = __float2bfloat16(v.y);
    __nv_bfloat16 c = __float2bfloat16(v.z), d = __float2bfloat16(v.w);
    __nv_bfloat16 e = __float2bfloat16(v.x - __bfloat162float(a));
    __nv_bfloat16 f = __float2bfloat16(v.y - __bfloat162float(b));
    __nv_bfloat16 g = __float2bfloat16(v.z - __bfloat162float(c));
    __nv_bfloat16 h = __float2bfloat16(v.w - __bfloat162float(d));
    __nv_bfloat162 hh0(a, b), hh1(c, d), ll0(e, f), ll1(g, h);
    h0 = *(uint32_t*)&hh0; h1 = *(uint32_t*)&hh1;
    l0 = *(uint32_t*)&ll0; l1 = *(uint32_t*)&ll1;
}
__device__ __forceinline__ void packh4(float4 v, uint32_t& h0, uint32_t& h1) {
    __nv_bfloat162 p0(__float2bfloat16(v.x), __float2bfloat16(v.y));
    __nv_bfloat162 p1(__float2bfloat16(v.z), __float2bfloat16(v.w));
    h0 = *(uint32_t*)&p0; h1 = *(uint32_t*)&p1;
}

// ---------------- dtype detection + count zeroing ----------------------------
__global__ void k_detect(const int* label, const int* lb) {
    __shared__ int nz_la, nz_lb;
    int t = threadIdx.x;
    if (t == 0) { nz_la = 0; nz_lb = 0; }
    __syncthreads();
    if (t < 64) {
        int w = 2 * (t * 128) + 1;
        if (label[w] != 0) atomicOr(&nz_la, 1);
        if (lb[w]    != 0) atomicOr(&nz_lb, 1);
    }
    __syncthreads();
    if (t == 0) g_is64 = (nz_la ? 0 : 1) | (nz_lb ? 0 : 2);
    for (int i = t; i < NSEG; i += blockDim.x) g_cnt[i] = 0;
}
__device__ __forceinline__ int ld_idx(const int* p, int i, bool is64) {
    return is64 ? p[2 * i] : p[i];
}

// ---------------- seg ids, counts, batch boundaries --------------------------
__global__ void k_prep(const int* label, const int* lb) {
    bool la64 = (g_is64 & 1) != 0, lb64 = (g_is64 & 2) != 0;
    int i = blockIdx.x * blockDim.x + threadIdx.x;
    if (i < N_) {
        int la = ld_idx(label, i, la64);
        int b  = ld_idx(lb,    i, lb64);
        int s  = b * NL + la;
        g_seg[i] = s;
        atomicAdd(&g_cnt[s], 1);
    }
    if (blockIdx.x == 0 && threadIdx.x <= NB) {
        int target = threadIdx.x;
        int lo = 0, hi = N_;
        while (lo < hi) {
            int mid = (lo + hi) >> 1;
            if (ld_idx(lb, mid, lb64) < target) lo = mid + 1; else hi = mid;
        }
        g_bstart[target] = lo;
    }
}

// ---------------- prefix scan over seg counts --------------------------------
__global__ void k_scan() {
    __shared__ int sh[1024];
    int t = threadIdx.x;
    int base = t * 4;
    int c[4];
    #pragma unroll
    for (int i = 0; i < 4; i++) c[i] = (base + i < NSEG) ? g_cnt[base + i] : 0;
    int tot = c[0] + c[1] + c[2] + c[3];
    sh[t] = tot;
    __syncthreads();
    int run = tot;
    for (int d = 1; d < 1024; d <<= 1) {
        int v = (t >= d) ? sh[t - d] : 0;
        __syncthreads();
        run += v; sh[t] = run;
        __syncthreads();
    }
    int excl = (t > 0) ? sh[t - 1] : 0;
    int p = excl;
    #pragma unroll
    for (int i = 0; i < 4; i++) {
        if (base + i <= NSEG) g_off[base + i] = p;
        if (base + i <  NSEG) g_cur[base + i] = p;
        p += c[i];
    }
}

// ---------------- scatter rows by segment ------------------------------------
__global__ void k_scatter() {
    int i = blockIdx.x * blockDim.x + threadIdx.x;
    int s = g_seg[i];
    int pos = atomicAdd(&g_cur[s], 1);
    g_rows[pos] = i;
}

// ---------------- weight hi/lo conversion ------------------------------------
__global__ void k_convw(const float* __restrict__ W1, const float* __restrict__ W2,
                        const float* __restrict__ b1, const float* __restrict__ b2) {
    int i = blockIdx.x * blockDim.x + threadIdx.x;   // float4 index over 512x2048
    int e = i * 4;
    int row = e >> 11;
    int col = e & 2047;
    const float* src = (row < 256) ? (W1 + (size_t)row * D_ + col)
                                   : (W2 + (size_t)(row - 256) * D_ + col);
    float4 v = *(const float4*)src;
    uint32_t h0, h1, l0, l1;
    pack_hilo(v, h0, h1, l0, l1);
    ((uint2*)g_bhi)[i] = make_uint2(h0, h1);
    ((uint2*)g_blo)[i] = make_uint2(l0, l1);
    if (blockIdx.x == 0 && threadIdx.x < P_)
        g_bias[threadIdx.x] = b1[threadIdx.x] + b2[threadIdx.x];
}

// ---------------- segment sums: sorted float4 gather, register acc ------------
__global__ void k_segsum(const float* __restrict__ x) {
    int c0   = blockIdx.x * 64;
    int s    = blockIdx.y * 16 + (threadIdx.x >> 4);
    int col4 = (threadIdx.x & 15) * 4;
    int i0 = g_off[s], i1 = g_off[s + 1];
    float4 a0 = make_float4(0.f, 0.f, 0.f, 0.f);
    float4 a1 = make_float4(0.f, 0.f, 0.f, 0.f);
    int i = i0;
    for (; i + 2 <= i1; i += 2) {
        int r0 = g_rows[i], r1 = g_rows[i + 1];
        float4 v0 = *(const float4*)(x + (size_t)r0 * D_ + c0 + col4);
        float4 v1 = *(const float4*)(x + (size_t)r1 * D_ + c0 + col4);
        a0.x += v0.x; a0.y += v0.y; a0.z += v0.z; a0.w += v0.w;
        a1.x += v1.x; a1.y += v1.y; a1.z += v1.z; a1.w += v1.w;
    }
    if (i < i1) {
        float4 v = *(const float4*)(x + (size_t)g_rows[i] * D_ + c0 + col4);
        a0.x += v.x; a0.y += v.y; a0.z += v.z; a0.w += v.w;
    }
    float4 r = make_float4(a0.x + a1.x, a0.y + a1.y, a0.z + a1.z, a0.w + a1.w);
    *(float4*)(g_sumx + (size_t)s * D_ + c0 + col4) = r;
}

// =============== main GEMM: out = x @ W1^T (3-term bf16), plain store ========
#define STAGE_B 24576
#define SMEM_REQ (NST * STAGE_B)

__device__ __forceinline__ void ldgA(const float* __restrict__ Arows, int kt,
                                     int tid, float4* areg) {
    int row = tid >> 2, h = tid & 3;                 // 4 thr/row, 8 floats each
    const float4* p = (const float4*)(Arows + (size_t)row * D_ + (kt << 5) + h * 8);
    areg[0] = p[0]; areg[1] = p[1];
}
__device__ __forceinline__ void stsA(uint32_t sg, int tid, const float4* areg) {
    int row = tid >> 2, h = tid & 3;
    uint32_t h0a, h1a, l0a, l1a, h0b, h1b, l0b, l1b;
    pack_hilo(areg[0], h0a, h1a, l0a, l1a);
    pack_hilo(areg[1], h0b, h1b, l0b, l1b);
    uint32_t o = swz(row * 64 + h * 16);
    sts16(sg + o,        h0a, h1a, h0b, h1b);        // A_hi
    sts16(sg + 4096 + o, l0a, l1a, l0b, l1b);        // A_lo
}
__device__ __forceinline__ void ldB(const __nv_bfloat16* Bh, const __nv_bfloat16* Bl,
                                    int kt, uint32_t sg, int tid) {
    int k0 = kt << 5;
    const char* gBh = (const char*)(Bh + k0);
    const char* gBl = (const char*)(Bl + k0);
    #pragma unroll
    for (int i = 0; i < 2; i++) {
        int idx = i * 256 + tid;
        int row = idx >> 2, c = idx & 3;
        uint32_t off = swz(row * 64 + c * 16);
        cp16(sg + 8192  + off, gBh + (size_t)row * (D_ * 2) + c * 16);
        cp16(sg + 16384 + off, gBl + (size_t)row * (D_ * 2) + c * 16);
    }
}

__global__ void __launch_bounds__(256, 3) k_gemm(const float* __restrict__ x,
                                                 float* __restrict__ out) {
    extern __shared__ __align__(128) char smem[];
    uint32_t sbase = smem_u32(smem);
    int tid = threadIdx.x, lane = tid & 31, wid = tid >> 5;
    int wm = wid & 1, wn = wid >> 1;                 // warp grid 2(M) x 4(N)
    int n0 = blockIdx.x * 128, m0 = blockIdx.y * 64;
    const float* Arows = x + (size_t)m0 * D_;
    const __nv_bfloat16* Bh = g_bhi + (size_t)n0 * D_;
    const __nv_bfloat16* Bl = g_blo + (size_t)n0 * D_;
    const int ktn = 64;

    float d[2][4][4];
    #pragma unroll
    for (int i = 0; i < 2; i++)
        #pragma unroll
        for (int j = 0; j < 4; j++)
            #pragma unroll
            for (int k = 0; k < 4; k++) d[i][j][k] = 0.0f;

    float4 areg[2];
    ldgA(Arows, 0, tid, areg);
    stsA(sbase, tid, areg);
    ldB(Bh, Bl, 0, sbase, tid); CP_COMMIT();
    ldgA(Arows, 1, tid, areg);
    ldB(Bh, Bl, 1, sbase + STAGE_B, tid); CP_COMMIT();

    uint32_t aoff[2], boff[2];
    #pragma unroll
    for (int s = 0; s < 2; s++) {
        int arow = wm * 32 + (lane & 15);
        int acol = s * 32 + (lane >> 4) * 16;
        aoff[s] = swz(arow * 64 + acol);
        int brow = wn * 32 + ((lane >> 4) & 1) * 8 + (lane & 7);
        int bcol = s * 32 + ((lane >> 3) & 1) * 16;
        boff[s] = swz(brow * 64 + bcol);
    }

    for (int kt = 0; kt < ktn; kt++) {
        CP_WAIT1();
        __syncthreads();
        if (kt + 1 < ktn)
            stsA(sbase + ((kt + 1) % NST) * STAGE_B, tid, areg);
        if (kt + 2 < ktn) {
            ldgA(Arows, kt + 2, tid, areg);
            ldB(Bh, Bl, kt + 2, sbase + ((kt + 2) % NST) * STAGE_B, tid);
        }
        CP_COMMIT();

        uint32_t sAh = sbase + (kt % NST) * STAGE_B;
        uint32_t sAl = sAh + 4096;
        uint32_t sBh = sAh + 8192;
        uint32_t sBl = sAh + 16384;
        #pragma unroll
        for (int s = 0; s < 2; s++) {
            uint32_t ah[2][4], al[2][4], bh[4][2], bl[4][2];
            #pragma unroll
            for (int f = 0; f < 2; f++)
                ldm4(sAh + f * 1024 + aoff[s], ah[f][0], ah[f][1], ah[f][2], ah[f][3]);
            #pragma unroll
            for (int p = 0; p < 2; p++)
                ldm4(sBh + p * 1024 + boff[s],
                     bh[2 * p][0], bh[2 * p][1], bh[2 * p + 1][0], bh[2 * p + 1][1]);
            #pragma unroll
            for (int p = 0; p < 2; p++)
                ldm4(sBl + p * 1024 + boff[s],
                     bl[2 * p][0], bl[2 * p][1], bl[2 * p + 1][0], bl[2 * p + 1][1]);
            #pragma unroll
            for (int f = 0; f < 2; f++)
                ldm4(sAl + f * 1024 + aoff[s], al[f][0], al[f][1], al[f][2], al[f][3]);
            #pragma unroll
            for (int mf = 0; mf < 2; mf++)
                #pragma unroll
                for (int nf = 0; nf < 4; nf++)
                    mma16816(d[mf][nf], ah[mf], bh[nf]);
            #pragma unroll
            for (int mf = 0; mf < 2; mf++)
                #pragma unroll
                for (int nf = 0; nf < 4; nf++)
                    mma16816(d[mf][nf], ah[mf], bl[nf]);
            #pragma unroll
            for (int mf = 0; mf < 2; mf++)
                #pragma unroll
                for (int nf = 0; nf < 4; nf++)
                    mma16816(d[mf][nf], al[mf], bh[nf]);
        }
    }
    CP_WAIT0();

    // plain store; g_M added later by k_fixup (computed concurrently)
    #pragma unroll
    for (int mf = 0; mf < 2; mf++) {
        int r0 = m0 + wm * 32 + mf * 16 + (lane >> 2);
        #pragma unroll
        for (int nf = 0; nf < 4; nf++) {
            int c = n0 + wn * 32 + nf * 8 + (lane & 3) * 2;
            *(float2*)(out + (size_t)r0 * P_ + c)
                = make_float2(d[mf][nf][0], d[mf][nf][1]);
            *(float2*)(out + (size_t)(r0 + 8) * P_ + c)
                = make_float2(d[mf][nf][2], d[mf][nf][3]);
        }
    }
}

// =============== mean GEMM: g_mpart[ks] = segsum_x @ W2^T (1-term bf16) ======
#define MSTAGE_B 12288
#define MSMEM_REQ (NST * MSTAGE_B)

__device__ __forceinline__ void stsA1(uint32_t sg, int tid, const float4* areg) {
    int row = tid >> 2, h = tid & 3;
    uint32_t h0, h1, h2, h3;
    packh4(areg[0], h0, h1);
    packh4(areg[1], h2, h3);
    sts16(sg + swz(row * 64 + h * 16), h0, h1, h2, h3);
}
__device__ __forceinline__ void ldB1(const char* Bh, int kt, uint32_t sg, int tid) {
    int k0 = kt << 6;   // bytes
    #pragma unroll
    for (int i = 0; i < 2; i++) {
        int idx = i * 256 + tid;
        int row = idx >> 2, c = idx & 3;
        uint32_t off = swz(row * 64 + c * 16);
        cp16(sg + 4096 + off, Bh + (size_t)row * (D_ * 2) + k0 + c * 16);
    }
}

__global__ void __launch_bounds__(256, 3) k_mgemm() {
    extern __shared__ __align__(128) char smem[];
    uint32_t sbase = smem_u32(smem);
    int tid = threadIdx.x, lane = tid & 31, wid = tid >> 5;
    int wm = wid & 1, wn = wid >> 1;
    int n0 = blockIdx.x * 128, m0 = blockIdx.y * 64, ks = blockIdx.z;
    const float* Arows = g_sumx + (size_t)m0 * D_ + ks * 512;
    const char*  Bh    = (const char*)(g_bhi + (size_t)(256 + n0) * D_ + ks * 512);
    float* dst = g_mpart + (size_t)ks * NSEG * P_ + (size_t)m0 * P_ + n0;
    const int ktn = 16;

    float d[2][4][4];
    #pragma unroll
    for (int i = 0; i < 2; i++)
        #pragma unroll
        for (int j = 0; j < 4; j++)
            #pragma unroll
            for (int k = 0; k < 4; k++) d[i][j][k] = 0.0f;

    float4 areg[2];
    ldgA(Arows, 0, tid, areg);
    stsA1(sbase, tid, areg);
    ldB1(Bh, 0, sbase, tid); CP_COMMIT();
    ldgA(Arows, 1, tid, areg);
    ldB1(Bh, 1, sbase + MSTAGE_B, tid); CP_COMMIT();

    uint32_t aoff[2], boff[2];
    #pragma unroll
    for (int s = 0; s < 2; s++) {
        int arow = wm * 32 + (lane & 15);
        int acol = s * 32 + (lane >> 4) * 16;
        aoff[s] = swz(arow * 64 + acol);
        int brow = wn * 32 + ((lane >> 4) & 1) * 8 + (lane & 7);
        int bcol = s * 32 + ((lane >> 3) & 1) * 16;
        boff[s] = swz(brow * 64 + bcol);
    }

    for (int kt = 0; kt < ktn; kt++) {
        CP_WAIT1();
        __syncthreads();
        if (kt + 1 < ktn)
            stsA1(sbase + ((kt + 1) % NST) * MSTAGE_B, tid, areg);
        if (kt + 2 < ktn) {
            ldgA(Arows, kt + 2, tid, areg);
            ldB1(Bh, kt + 2, sbase + ((kt + 2) % NST) * MSTAGE_B, tid);
        }
        CP_COMMIT();

        uint32_t sA = sbase + (kt % NST) * MSTAGE_B;
        uint32_t sB = sA + 4096;
        #pragma unroll
        for (int s = 0; s < 2; s++) {
            uint32_t a[2][4], b[4][2];
            #pragma unroll
            for (int f = 0; f < 2; f++)
                ldm4(sA + f * 1024 + aoff[s], a[f][0], a[f][1], a[f][2], a[f][3]);
            #pragma unroll
            for (int p = 0; p < 2; p++)
                ldm4(sB + p * 1024 + boff[s],
                     b[2 * p][0], b[2 * p][1], b[2 * p + 1][0], b[2 * p + 1][1]);
            #pragma unroll
            for (int mf = 0; mf < 2; mf++)
                #pragma unroll
                for (int nf = 0; nf < 4; nf++)
                    mma16816(d[mf][nf], a[mf], b[nf]);
        }
    }
    CP_WAIT0();

    #pragma unroll
    for (int mf = 0; mf < 2; mf++) {
        #pragma unroll
        for (int nf = 0; nf < 4; nf++) {
            int r = wm * 32 + mf * 16 + (lane >> 2);
            int c = wn * 32 + nf * 8 + (lane & 3) * 2;
            *(float2*)(dst + (size_t)r * P_ + c)
                = make_float2(d[mf][nf][0], d[mf][nf][1]);
            *(float2*)(dst + (size_t)(r + 8) * P_ + c)
                = make_float2(d[mf][nf][2], d[mf][nf][3]);
        }
    }
}

// ---------------- reduce K-split parts ---------------------------------------
__global__ void k_mred() {
    int i = blockIdx.x * blockDim.x + threadIdx.x;
    float s = g_mpart[i] + g_mpart[NSEG * P_ + i]
            + g_mpart[2 * NSEG * P_ + i] + g_mpart[3 * NSEG * P_ + i];
    g_sum_bl2[i] = s;
}

// ---------------- per-batch sums from per-seg sums ---------------------------
__global__ void k_sumb() {
    int b = blockIdx.x, h = blockIdx.y;
    int col = h * 128 + threadIdx.x;
    const float* base = g_sum_bl2 + (size_t)(b * NL) * P_ + col;
    float acc = 0.0f;
    #pragma unroll 4
    for (int l = 0; l < NL; l++) acc += base[(size_t)l * P_];
    g_sum_b2[b * P_ + col] = acc;
}

// ---------------- per-segment output addend ----------------------------------
__global__ void k_minv() {
    int s = blockIdx.x, t = threadIdx.x;
    int b = s / NL;
    int cb = g_bstart[b + 1] - g_bstart[b];
    int d = cb - g_cnt[s];
    float inv = (d > 0) ? (1.0f / (float)d) : 0.0f;
    float m = (g_sum_b2[b * P_ + t] - g_sum_bl2[(size_t)s * P_ + t]) * inv;
    g_M[(size_t)s * P_ + t] = m + g_bias[t];
}

// ---------------- final gather-add (512 thr, 2 float4/thread) ----------------
__global__ void k_fixup(float* __restrict__ out) {
    int i = blockIdx.x * (blockDim.x * 2) + threadIdx.x;  // float4 index
    #pragma unroll
    for (int u = 0; u < 2; u++) {
        int idx = i + u * blockDim.x;
        int row = idx >> 6;
        int c4  = (idx & 63) << 2;
        int s = g_seg[row];
        float4 o = *(float4*)(out + (size_t)row * P_ + c4);
        float4 m = *(const float4*)(g_M + (size_t)s * P_ + c4);
        o.x += m.x; o.y += m.y; o.z += m.z; o.w += m.w;
        *(float4*)(out + (size_t)row * P_ + c4) = o;
    }
}

// ---------------- launch: two-stream fork/join inside graph capture ----------
extern "C" void kernel_launch(void* const* d_in, const int* in_sizes, int n_in,
                              void* d_out, int out_size) {
    const float* x     = (const float*)d_in[0];
    const int*   label = (const int*)  d_in[1];
    const int*   lb    = (const int*)  d_in[2];
    const float* W1_w  = (const float*)d_in[3];
    const float* W1_b  = (const float*)d_in[4];
    const float* W2_w  = (const float*)d_in[5];
    const float* W2_b  = (const float*)d_in[6];
    float* out = (float*)d_out;

    cudaFuncSetAttribute(k_gemm,  cudaFuncAttributeMaxDynamicSharedMemorySize, SMEM_REQ);
    cudaFuncSetAttribute(k_mgemm, cudaFuncAttributeMaxDynamicSharedMemorySize, MSMEM_REQ);

    cudaStream_t sB;
    cudaStreamCreateWithFlags(&sB, cudaStreamNonBlocking);
    cudaEvent_t evFork, evConvw, evB;
    cudaEventCreateWithFlags(&evFork,  cudaEventDisableTiming);
    cudaEventCreateWithFlags(&evConvw, cudaEventDisableTiming);
    cudaEventCreateWithFlags(&evB,     cudaEventDisableTiming);

    // fork aux stream from the capturing (default) stream
    cudaEventRecord(evFork, 0);
    cudaStreamWaitEvent(sB, evFork, 0);

    // ---- stream B: segment bookkeeping + mean pipeline ----
    k_detect <<<1, 256, 0, sB>>>(label, lb);
    k_prep   <<<N_ / 256, 256, 0, sB>>>(label, lb);
    k_scan   <<<1, 1024, 0, sB>>>();
    k_scatter<<<N_ / 256, 256, 0, sB>>>();
    k_segsum <<<dim3(D_ / 64, NSEG / 16), 256, 0, sB>>>(x);

    // ---- default stream: weight conversion, then main GEMM ----
    k_convw<<<(512 * D_ / 4) / 256, 256>>>(W1_w, W2_w, W1_b, W2_b);
    cudaEventRecord(evConvw, 0);
    cudaStreamWaitEvent(sB, evConvw, 0);   // mgemm needs g_bhi (W2 half) + g_bias

    k_mgemm<<<dim3(2, NSEG / 64, 4), 256, MSMEM_REQ, sB>>>();
    k_mred <<<(NSEG * P_) / 256, 256, 0, sB>>>();
    k_sumb <<<dim3(NB, 2), 128, 0, sB>>>();
    k_minv <<<NSEG, 256, 0, sB>>>();
    cudaEventRecord(evB, sB);

    k_gemm<<<dim3(2, 256), 256, SMEM_REQ>>>(x, out);

    // join: fixup needs both out (default) and g_M/g_seg (stream B)
    cudaStreamWaitEvent(0, evB, 0);
    k_fixup<<<(N_ * P_ / 4) / 1024, 512>>>(out);
}

// round 17
// speedup vs baseline: 1.0854x; 1.0133x over previous
#include <cuda_runtime.h>
#include <cuda_bf16.h>
#include <cstdint>

#define N_   16384
#define D_   2048
#define P_   256
#define NB   32
#define NL   100
#define NSEG (NB*NL)
#define NST  3          // pipeline stages

// ---------------- scratch globals (no allocations allowed) -------------------
__device__ __nv_bfloat16 g_bhi[512 * D_];   // [W1;W2] hi
__device__ __nv_bfloat16 g_blo[512 * D_];   // [W1;W2] lo (W2 half unused)
__device__ float g_sumx[NSEG * D_];         // exact fp32 segsum of x
__device__ float g_mpart[4 * NSEG * P_];    // K-split partials of segsum@W2^T
__device__ float g_sum_bl2[NSEG * P_];
__device__ float g_sum_b2 [NB   * P_];
__device__ float g_M[NSEG * P_];
__device__ float g_bias[P_];
__device__ int   g_cnt[NSEG];
__device__ int   g_off[NSEG + 1];
__device__ int   g_cur[NSEG];
__device__ int   g_rows[N_];
__device__ int   g_seg[N_];
__device__ int   g_bstart[NB + 1];
__device__ int   g_is64;

// ---------------- PTX helpers ------------------------------------------------
__device__ __forceinline__ uint32_t smem_u32(const void* p) {
    uint32_t a;
    asm("{ .reg .u64 t; cvta.to.shared.u64 t, %1; cvt.u32.u64 %0, t; }" : "=r"(a) : "l"(p));
    return a;
}
__device__ __forceinline__ void cp16(uint32_t dst, const void* src) {
    asm volatile("cp.async.cg.shared.global [%0], [%1], 16;" :: "r"(dst), "l"(src));
}
#define CP_COMMIT() asm volatile("cp.async.commit_group;" ::: "memory")
#define CP_WAIT1()  asm volatile("cp.async.wait_group 1;"  ::: "memory")
#define CP_WAIT0()  asm volatile("cp.async.wait_group 0;"  ::: "memory")

__device__ __forceinline__ uint32_t swz(uint32_t o) {   // 64B-row swizzle
    return o ^ ((o >> 3) & 0x30);
}
__device__ __forceinline__ void ldm4(uint32_t addr, uint32_t& r0, uint32_t& r1,
                                     uint32_t& r2, uint32_t& r3) {
    asm volatile("ldmatrix.sync.aligned.m8n8.x4.shared.b16 {%0,%1,%2,%3}, [%4];"
                 : "=r"(r0), "=r"(r1), "=r"(r2), "=r"(r3) : "r"(addr));
}
__device__ __forceinline__ void mma16816(float* d, const uint32_t* a,
                                         const uint32_t* b) {
    asm volatile(
        "mma.sync.aligned.m16n8k16.row.col.f32.bf16.bf16.f32 "
        "{%0,%1,%2,%3}, {%4,%5,%6,%7}, {%8,%9}, {%0,%1,%2,%3};"
        : "+f"(d[0]), "+f"(d[1]), "+f"(d[2]), "+f"(d[3])
        : "r"(a[0]), "r"(a[1]), "r"(a[2]), "r"(a[3]), "r"(b[0]), "r"(b[1]));
}
__device__ __forceinline__ void sts16(uint32_t addr, uint32_t r0, uint32_t r1,
                                      uint32_t r2, uint32_t r3) {
    asm volatile("st.shared.v4.b32 [%0], {%1,%2,%3,%4};"
                 :: "r"(addr), "r"(r0), "r"(r1), "r"(r2), "r"(r3) : "memory");
}

// 4 floats -> hi bf16x2 pair + lo bf16x2 pair
__device__ __forceinline__ void pack_hilo(float4 v, uint32_t& h0, uint32_t& h1,
                                          uint32_t& l0, uint32_t& l1) {
    __nv_bfloat16 a = __float2bfloat16(v.x), b = __float2bfloat16(v.y);
    __nv_bfloat16 c = __float2bfloat16(v.z), d = __float2bfloat16(v.w);
    __nv_bfloat16 e = __float2bfloat16(v.x - __bfloat162float(a));
    __nv_bfloat16 f = __float2bfloat16(v.y - __bfloat162float(b));
    __nv_bfloat16 g = __float2bfloat16(v.z - __bfloat162float(c));
    __nv_bfloat16 h = __float2bfloat16(v.w - __bfloat162float(d));
    __nv_bfloat162 hh0(a, b), hh1(c, d), ll0(e, f), ll1(g, h);
    h0 = *(uint32_t*)&hh0; h1 = *(uint32_t*)&hh1;
    l0 = *(uint32_t*)&ll0; l1 = *(uint32_t*)&ll1;
}
__device__ __forceinline__ void packh4(float4 v, uint32_t& h0, uint32_t& h1) {
    __nv_bfloat162 p0(__float2bfloat16(v.x), __float2bfloat16(v.y));
    __nv_bfloat162 p1(__float2bfloat16(v.z), __float2bfloat16(v.w));
    h0 = *(uint32_t*)&p0; h1 = *(uint32_t*)&p1;
}

// ---------------- dtype detection + count zeroing ----------------------------
__global__ void k_detect(const int* label, const int* lb) {
    __shared__ int nz_la, nz_lb;
    int t = threadIdx.x;
    if (t == 0) { nz_la = 0; nz_lb = 0; }
    __syncthreads();
    if (t < 64) {
        int w = 2 * (t * 128) + 1;
        if (label[w] != 0) atomicOr(&nz_la, 1);
        if (lb[w]    != 0) atomicOr(&nz_lb, 1);
    }
    __syncthreads();
    if (t == 0) g_is64 = (nz_la ? 0 : 1) | (nz_lb ? 0 : 2);
    for (int i = t; i < NSEG; i += blockDim.x) g_cnt[i] = 0;
}
__device__ __forceinline__ int ld_idx(const int* p, int i, bool is64) {
    return is64 ? p[2 * i] : p[i];
}

// ---------------- seg ids, counts, batch boundaries --------------------------
__global__ void k_prep(const int* label, const int* lb) {
    bool la64 = (g_is64 & 1) != 0, lb64 = (g_is64 & 2) != 0;
    int i = blockIdx.x * blockDim.x + threadIdx.x;
    if (i < N_) {
        int la = ld_idx(label, i, la64);
        int b  = ld_idx(lb,    i, lb64);
        int s  = b * NL + la;
        g_seg[i] = s;
        atomicAdd(&g_cnt[s], 1);
    }
    if (blockIdx.x == 0 && threadIdx.x <= NB) {
        int target = threadIdx.x;
        int lo = 0, hi = N_;
        while (lo < hi) {
            int mid = (lo + hi) >> 1;
            if (ld_idx(lb, mid, lb64) < target) lo = mid + 1; else hi = mid;
        }
        g_bstart[target] = lo;
    }
}

// ---------------- prefix scan over seg counts --------------------------------
__global__ void k_scan() {
    __shared__ int sh[1024];
    int t = threadIdx.x;
    int base = t * 4;
    int c[4];
    #pragma unroll
    for (int i = 0; i < 4; i++) c[i] = (base + i < NSEG) ? g_cnt[base + i] : 0;
    int tot = c[0] + c[1] + c[2] + c[3];
    sh[t] = tot;
    __syncthreads();
    int run = tot;
    for (int d = 1; d < 1024; d <<= 1) {
        int v = (t >= d) ? sh[t - d] : 0;
        __syncthreads();
        run += v; sh[t] = run;
        __syncthreads();
    }
    int excl = (t > 0) ? sh[t - 1] : 0;
    int p = excl;
    #pragma unroll
    for (int i = 0; i < 4; i++) {
        if (base + i <= NSEG) g_off[base + i] = p;
        if (base + i <  NSEG) g_cur[base + i] = p;
        p += c[i];
    }
}

// ---------------- scatter rows by segment ------------------------------------
__global__ void k_scatter() {
    int i = blockIdx.x * blockDim.x + threadIdx.x;
    int s = g_seg[i];
    int pos = atomicAdd(&g_cur[s], 1);
    g_rows[pos] = i;
}

// ---------------- weight hi/lo conversion ------------------------------------
__global__ void k_convw(const float* __restrict__ W1, const float* __restrict__ W2,
                        const float* __restrict__ b1, const float* __restrict__ b2) {
    int i = blockIdx.x * blockDim.x + threadIdx.x;   // float4 index over 512x2048
    int e = i * 4;
    int row = e >> 11;
    int col = e & 2047;
    const float* src = (row < 256) ? (W1 + (size_t)row * D_ + col)
                                   : (W2 + (size_t)(row - 256) * D_ + col);
    float4 v = *(const float4*)src;
    uint32_t h0, h1, l0, l1;
    pack_hilo(v, h0, h1, l0, l1);
    ((uint2*)g_bhi)[i] = make_uint2(h0, h1);
    ((uint2*)g_blo)[i] = make_uint2(l0, l1);
    if (blockIdx.x == 0 && threadIdx.x < P_)
        g_bias[threadIdx.x] = b1[threadIdx.x] + b2[threadIdx.x];
}

// ---------------- segment sums: sorted float4 gather, register acc ------------
__global__ void k_segsum(const float* __restrict__ x) {
    int c0   = blockIdx.x * 64;
    int s    = blockIdx.y * 16 + (threadIdx.x >> 4);
    int col4 = (threadIdx.x & 15) * 4;
    int i0 = g_off[s], i1 = g_off[s + 1];
    float4 a0 = make_float4(0.f, 0.f, 0.f, 0.f);
    float4 a1 = make_float4(0.f, 0.f, 0.f, 0.f);
    int i = i0;
    for (; i + 2 <= i1; i += 2) {
        int r0 = g_rows[i], r1 = g_rows[i + 1];
        float4 v0 = *(const float4*)(x + (size_t)r0 * D_ + c0 + col4);
        float4 v1 = *(const float4*)(x + (size_t)r1 * D_ + c0 + col4);
        a0.x += v0.x; a0.y += v0.y; a0.z += v0.z; a0.w += v0.w;
        a1.x += v1.x; a1.y += v1.y; a1.z += v1.z; a1.w += v1.w;
    }
    if (i < i1) {
        float4 v = *(const float4*)(x + (size_t)g_rows[i] * D_ + c0 + col4);
        a0.x += v.x; a0.y += v.y; a0.z += v.z; a0.w += v.w;
    }
    float4 r = make_float4(a0.x + a1.x, a0.y + a1.y, a0.z + a1.z, a0.w + a1.w);
    *(float4*)(g_sumx + (size_t)s * D_ + c0 + col4) = r;
}

// =============== main GEMM: out = x @ W1^T (3-term bf16), plain store ========
#define STAGE_B 24576
#define SMEM_REQ (NST * STAGE_B)

__device__ __forceinline__ void ldgA(const float* __restrict__ Arows, int kt,
                                     int tid, float4* areg) {
    int row = tid >> 2, h = tid & 3;                 // 4 thr/row, 8 floats each
    const float4* p = (const float4*)(Arows + (size_t)row * D_ + (kt << 5) + h * 8);
    areg[0] = p[0]; areg[1] = p[1];
}
__device__ __forceinline__ void stsA(uint32_t sg, int tid, const float4* areg) {
    int row = tid >> 2, h = tid & 3;
    uint32_t h0a, h1a, l0a, l1a, h0b, h1b, l0b, l1b;
    pack_hilo(areg[0], h0a, h1a, l0a, l1a);
    pack_hilo(areg[1], h0b, h1b, l0b, l1b);
    uint32_t o = swz(row * 64 + h * 16);
    sts16(sg + o,        h0a, h1a, h0b, h1b);        // A_hi
    sts16(sg + 4096 + o, l0a, l1a, l0b, l1b);        // A_lo
}
__device__ __forceinline__ void ldB(const __nv_bfloat16* Bh, const __nv_bfloat16* Bl,
                                    int kt, uint32_t sg, int tid) {
    int k0 = kt << 5;
    const char* gBh = (const char*)(Bh + k0);
    const char* gBl = (const char*)(Bl + k0);
    #pragma unroll
    for (int i = 0; i < 2; i++) {
        int idx = i * 256 + tid;
        int row = idx >> 2, c = idx & 3;
        uint32_t off = swz(row * 64 + c * 16);
        cp16(sg + 8192  + off, gBh + (size_t)row * (D_ * 2) + c * 16);
        cp16(sg + 16384 + off, gBl + (size_t)row * (D_ * 2) + c * 16);
    }
}

__global__ void __launch_bounds__(256, 3) k_gemm(const float* __restrict__ x,
                                                 float* __restrict__ out) {
    extern __shared__ __align__(128) char smem[];
    uint32_t sbase = smem_u32(smem);
    int tid = threadIdx.x, lane = tid & 31, wid = tid >> 5;
    int wm = wid & 1, wn = wid >> 1;                 // warp grid 2(M) x 4(N)
    int n0 = blockIdx.x * 128, m0 = blockIdx.y * 64;
    const float* Arows = x + (size_t)m0 * D_;
    const __nv_bfloat16* Bh = g_bhi + (size_t)n0 * D_;
    const __nv_bfloat16* Bl = g_blo + (size_t)n0 * D_;
    const int ktn = 64;

    float d[2][4][4];
    #pragma unroll
    for (int i = 0; i < 2; i++)
        #pragma unroll
        for (int j = 0; j < 4; j++)
            #pragma unroll
            for (int k = 0; k < 4; k++) d[i][j][k] = 0.0f;

    float4 areg[2];
    ldgA(Arows, 0, tid, areg);
    stsA(sbase, tid, areg);
    ldB(Bh, Bl, 0, sbase, tid); CP_COMMIT();
    ldgA(Arows, 1, tid, areg);
    ldB(Bh, Bl, 1, sbase + STAGE_B, tid); CP_COMMIT();

    uint32_t aoff[2], boff[2];
    #pragma unroll
    for (int s = 0; s < 2; s++) {
        int arow = wm * 32 + (lane & 15);
        int acol = s * 32 + (lane >> 4) * 16;
        aoff[s] = swz(arow * 64 + acol);
        int brow = wn * 32 + ((lane >> 4) & 1) * 8 + (lane & 7);
        int bcol = s * 32 + ((lane >> 3) & 1) * 16;
        boff[s] = swz(brow * 64 + bcol);
    }

    for (int kt = 0; kt < ktn; kt++) {
        CP_WAIT1();
        __syncthreads();
        if (kt + 1 < ktn)
            stsA(sbase + ((kt + 1) % NST) * STAGE_B, tid, areg);
        if (kt + 2 < ktn) {
            ldgA(Arows, kt + 2, tid, areg);
            ldB(Bh, Bl, kt + 2, sbase + ((kt + 2) % NST) * STAGE_B, tid);
        }
        CP_COMMIT();

        uint32_t sAh = sbase + (kt % NST) * STAGE_B;
        uint32_t sAl = sAh + 4096;
        uint32_t sBh = sAh + 8192;
        uint32_t sBl = sAh + 16384;
        #pragma unroll
        for (int s = 0; s < 2; s++) {
            uint32_t ah[2][4], al[2][4], bh[4][2], bl[4][2];
            #pragma unroll
            for (int f = 0; f < 2; f++)
                ldm4(sAh + f * 1024 + aoff[s], ah[f][0], ah[f][1], ah[f][2], ah[f][3]);
            #pragma unroll
            for (int p = 0; p < 2; p++)
                ldm4(sBh + p * 1024 + boff[s],
                     bh[2 * p][0], bh[2 * p][1], bh[2 * p + 1][0], bh[2 * p + 1][1]);
            #pragma unroll
            for (int p = 0; p < 2; p++)
                ldm4(sBl + p * 1024 + boff[s],
                     bl[2 * p][0], bl[2 * p][1], bl[2 * p + 1][0], bl[2 * p + 1][1]);
            #pragma unroll
            for (int f = 0; f < 2; f++)
                ldm4(sAl + f * 1024 + aoff[s], al[f][0], al[f][1], al[f][2], al[f][3]);
            #pragma unroll
            for (int mf = 0; mf < 2; mf++)
                #pragma unroll
                for (int nf = 0; nf < 4; nf++)
                    mma16816(d[mf][nf], ah[mf], bh[nf]);
            #pragma unroll
            for (int mf = 0; mf < 2; mf++)
                #pragma unroll
                for (int nf = 0; nf < 4; nf++)
                    mma16816(d[mf][nf], ah[mf], bl[nf]);
            #pragma unroll
            for (int mf = 0; mf < 2; mf++)
                #pragma unroll
                for (int nf = 0; nf < 4; nf++)
                    mma16816(d[mf][nf], al[mf], bh[nf]);
        }
    }
    CP_WAIT0();

    // plain store; g_M added later by k_fixup (computed concurrently)
    #pragma unroll
    for (int mf = 0; mf < 2; mf++) {
        int r0 = m0 + wm * 32 + mf * 16 + (lane >> 2);
        #pragma unroll
        for (int nf = 0; nf < 4; nf++) {
            int c = n0 + wn * 32 + nf * 8 + (lane & 3) * 2;
            *(float2*)(out + (size_t)r0 * P_ + c)
                = make_float2(d[mf][nf][0], d[mf][nf][1]);
            *(float2*)(out + (size_t)(r0 + 8) * P_ + c)
                = make_float2(d[mf][nf][2], d[mf][nf][3]);
        }
    }
}

// =============== mean GEMM: g_mpart[ks] = segsum_x @ W2^T (1-term bf16) ======
#define MSTAGE_B 12288
#define MSMEM_REQ (NST * MSTAGE_B)

__device__ __forceinline__ void stsA1(uint32_t sg, int tid, const float4* areg) {
    int row = tid >> 2, h = tid & 3;
    uint32_t h0, h1, h2, h3;
    packh4(areg[0], h0, h1);
    packh4(areg[1], h2, h3);
    sts16(sg + swz(row * 64 + h * 16), h0, h1, h2, h3);
}
__device__ __forceinline__ void ldB1(const char* Bh, int kt, uint32_t sg, int tid) {
    int k0 = kt << 6;   // bytes
    #pragma unroll
    for (int i = 0; i < 2; i++) {
        int idx = i * 256 + tid;
        int row = idx >> 2, c = idx & 3;
        uint32_t off = swz(row * 64 + c * 16);
        cp16(sg + 4096 + off, Bh + (size_t)row * (D_ * 2) + k0 + c * 16);
    }
}

__global__ void __launch_bounds__(256, 3) k_mgemm() {
    extern __shared__ __align__(128) char smem[];
    uint32_t sbase = smem_u32(smem);
    int tid = threadIdx.x, lane = tid & 31, wid = tid >> 5;
    int wm = wid & 1, wn = wid >> 1;
    int n0 = blockIdx.x * 128, m0 = blockIdx.y * 64, ks = blockIdx.z;
    const float* Arows = g_sumx + (size_t)m0 * D_ + ks * 512;
    const char*  Bh    = (const char*)(g_bhi + (size_t)(256 + n0) * D_ + ks * 512);
    float* dst = g_mpart + (size_t)ks * NSEG * P_ + (size_t)m0 * P_ + n0;
    const int ktn = 16;

    float d[2][4][4];
    #pragma unroll
    for (int i = 0; i < 2; i++)
        #pragma unroll
        for (int j = 0; j < 4; j++)
            #pragma unroll
            for (int k = 0; k < 4; k++) d[i][j][k] = 0.0f;

    float4 areg[2];
    ldgA(Arows, 0, tid, areg);
    stsA1(sbase, tid, areg);
    ldB1(Bh, 0, sbase, tid); CP_COMMIT();
    ldgA(Arows, 1, tid, areg);
    ldB1(Bh, 1, sbase + MSTAGE_B, tid); CP_COMMIT();

    uint32_t aoff[2], boff[2];
    #pragma unroll
    for (int s = 0; s < 2; s++) {
        int arow = wm * 32 + (lane & 15);
        int acol = s * 32 + (lane >> 4) * 16;
        aoff[s] = swz(arow * 64 + acol);
        int brow = wn * 32 + ((lane >> 4) & 1) * 8 + (lane & 7);
        int bcol = s * 32 + ((lane >> 3) & 1) * 16;
        boff[s] = swz(brow * 64 + bcol);
    }

    for (int kt = 0; kt < ktn; kt++) {
        CP_WAIT1();
        __syncthreads();
        if (kt + 1 < ktn)
            stsA1(sbase + ((kt + 1) % NST) * MSTAGE_B, tid, areg);
        if (kt + 2 < ktn) {
            ldgA(Arows, kt + 2, tid, areg);
            ldB1(Bh, kt + 2, sbase + ((kt + 2) % NST) * MSTAGE_B, tid);
        }
        CP_COMMIT();

        uint32_t sA = sbase + (kt % NST) * MSTAGE_B;
        uint32_t sB = sA + 4096;
        #pragma unroll
        for (int s = 0; s < 2; s++) {
            uint32_t a[2][4], b[4][2];
            #pragma unroll
            for (int f = 0; f < 2; f++)
                ldm4(sA + f * 1024 + aoff[s], a[f][0], a[f][1], a[f][2], a[f][3]);
            #pragma unroll
            for (int p = 0; p < 2; p++)
                ldm4(sB + p * 1024 + boff[s],
                     b[2 * p][0], b[2 * p][1], b[2 * p + 1][0], b[2 * p + 1][1]);
            #pragma unroll
            for (int mf = 0; mf < 2; mf++)
                #pragma unroll
                for (int nf = 0; nf < 4; nf++)
                    mma16816(d[mf][nf], a[mf], b[nf]);
        }
    }
    CP_WAIT0();

    #pragma unroll
    for (int mf = 0; mf < 2; mf++) {
        #pragma unroll
        for (int nf = 0; nf < 4; nf++) {
            int r = wm * 32 + mf * 16 + (lane >> 2);
            int c = wn * 32 + nf * 8 + (lane & 3) * 2;
            *(float2*)(dst + (size_t)r * P_ + c)
                = make_float2(d[mf][nf][0], d[mf][nf][1]);
            *(float2*)(dst + (size_t)(r + 8) * P_ + c)
                = make_float2(d[mf][nf][2], d[mf][nf][3]);
        }
    }
}

// ---------------- reduce K-split parts ---------------------------------------
__global__ void k_mred() {
    int i = blockIdx.x * blockDim.x + threadIdx.x;
    float s = g_mpart[i] + g_mpart[NSEG * P_ + i]
            + g_mpart[2 * NSEG * P_ + i] + g_mpart[3 * NSEG * P_ + i];
    g_sum_bl2[i] = s;
}

// ---------------- per-batch sums from per-seg sums ---------------------------
__global__ void k_sumb() {
    int b = blockIdx.x, h = blockIdx.y;
    int col = h * 128 + threadIdx.x;
    const float* base = g_sum_bl2 + (size_t)(b * NL) * P_ + col;
    float acc = 0.0f;
    #pragma unroll 4
    for (int l = 0; l < NL; l++) acc += base[(size_t)l * P_];
    g_sum_b2[b * P_ + col] = acc;
}

// ---------------- per-segment output addend ----------------------------------
__global__ void k_minv() {
    int s = blockIdx.x, t = threadIdx.x;
    int b = s / NL;
    int cb = g_bstart[b + 1] - g_bstart[b];
    int d = cb - g_cnt[s];
    float inv = (d > 0) ? (1.0f / (float)d) : 0.0f;
    float m = (g_sum_b2[b * P_ + t] - g_sum_bl2[(size_t)s * P_ + t]) * inv;
    g_M[(size_t)s * P_ + t] = m + g_bias[t];
}

// ---------------- final gather-add (512 thr, 2 float4/thread) ----------------
__global__ void k_fixup(float* __restrict__ out) {
    int i = blockIdx.x * (blockDim.x * 2) + threadIdx.x;  // float4 index
    #pragma unroll
    for (int u = 0; u < 2; u++) {
        int idx = i + u * blockDim.x;
        int row = idx >> 6;
        int c4  = (idx & 63) << 2;
        int s = g_seg[row];
        float4 o = *(float4*)(out + (size_t)row * P_ + c4);
        float4 m = *(const float4*)(g_M + (size_t)s * P_ + c4);
        o.x += m.x; o.y += m.y; o.z += m.z; o.w += m.w;
        *(float4*)(out + (size_t)row * P_ + c4) = o;
    }
}

// ---------------- launch: two-stream fork/join inside graph capture ----------
extern "C" void kernel_launch(void* const* d_in, const int* in_sizes, int n_in,
                              void* d_out, int out_size) {
    const float* x     = (const float*)d_in[0];
    const int*   label = (const int*)  d_in[1];
    const int*   lb    = (const int*)  d_in[2];
    const float* W1_w  = (const float*)d_in[3];
    const float* W1_b  = (const float*)d_in[4];
    const float* W2_w  = (const float*)d_in[5];
    const float* W2_b  = (const float*)d_in[6];
    float* out = (float*)d_out;

    cudaFuncSetAttribute(k_gemm,  cudaFuncAttributeMaxDynamicSharedMemorySize, SMEM_REQ);
    cudaFuncSetAttribute(k_mgemm, cudaFuncAttributeMaxDynamicSharedMemorySize, MSMEM_REQ);

    cudaStream_t sB;
    cudaStreamCreateWithFlags(&sB, cudaStreamNonBlocking);
    cudaEvent_t evConvw, evB;
    cudaEventCreateWithFlags(&evConvw, cudaEventDisableTiming);
    cudaEventCreateWithFlags(&evB,     cudaEventDisableTiming);

    // ---- default stream: weight conversion runs uncontended first ----
    k_convw<<<(512 * D_ / 4) / 256, 256>>>(W1_w, W2_w, W1_b, W2_b);
    cudaEventRecord(evConvw, 0);
    // fork aux stream AFTER convw so convw has the whole chip
    cudaStreamWaitEvent(sB, evConvw, 0);

    // ---- stream B: segment bookkeeping + mean pipeline ----
    k_detect <<<1, 256, 0, sB>>>(label, lb);
    k_prep   <<<N_ / 256, 256, 0, sB>>>(label, lb);
    k_scan   <<<1, 1024, 0, sB>>>();
    k_scatter<<<N_ / 256, 256, 0, sB>>>();
    k_segsum <<<dim3(D_ / 64, NSEG / 16), 256, 0, sB>>>(x);
    k_mgemm  <<<dim3(2, NSEG / 64, 4), 256, MSMEM_REQ, sB>>>();
    k_mred   <<<(NSEG * P_) / 256, 256, 0, sB>>>();
    k_sumb   <<<dim3(NB, 2), 128, 0, sB>>>();
    k_minv   <<<NSEG, 256, 0, sB>>>();
    cudaEventRecord(evB, sB);

    // ---- default stream: main GEMM ----
    k_gemm<<<dim3(2, 256), 256, SMEM_REQ>>>(x, out);

    // join: fixup needs both out (default) and g_M/g_seg (stream B)
    cudaStreamWaitEvent(0, evB, 0);
    k_fixup<<<(N_ * P_ / 4) / 1024, 512>>>(out);
}